// round 9
// baseline (speedup 1.0000x reference)
#include <cuda_runtime.h>
#include <cuda_bf16.h>
#include <cstdint>
#include <cstddef>

#define BATCH   4
#define CIN     64
#define COUT    128
#define HH      64
#define WW      1024
#define HO      32
#define WO      512
#define NPIX    65536
#define KTOT    1024
#define OUT0    8388608
#define AZI_C   0.006135923151542565f
#define INC_C   0.0073f

// Wc reordered: column k' = pos*64 + c, bf16 hi/lo
__device__ __nv_bfloat16 g_WcH[COUT * KTOT];
__device__ __nv_bfloat16 g_WcL[COUT * KTOT];
__device__ __nv_bfloat16 g_W2TH[CIN * CIN];   // [c][j]
__device__ __nv_bfloat16 g_W2TL[CIN * CIN];
__device__ float g_Ast[CIN * 16];             // [j][pos]

__device__ __forceinline__ uint32_t smem_u32(const void* p) {
    uint32_t a;
    asm("{ .reg .u64 t; cvta.to.shared.u64 t, %1; cvt.u32.u64 %0, t; }" : "=r"(a) : "l"(p));
    return a;
}
#define SWA(o) ((o) ^ (((o) >> 3) & 0x70))
#define SWC(o) ((o) ^ (((o) >> 5) & 0x70))

__device__ __forceinline__ void sts32(uint32_t saddr, uint32_t v) {
    asm volatile("st.shared.u32 [%0], %1;" :: "r"(saddr), "r"(v) : "memory");
}
__device__ __forceinline__ void cp16(uint32_t saddr, const void* gaddr) {
    asm volatile("cp.async.cg.shared.global [%0], [%1], 16;" :: "r"(saddr), "l"(gaddr));
}
#define CP_COMMIT() asm volatile("cp.async.commit_group;" ::: "memory")
#define CP_WAIT1()  asm volatile("cp.async.wait_group 1;" ::: "memory")
#define CP_WAIT0()  asm volatile("cp.async.wait_group 0;" ::: "memory")

__device__ __forceinline__ void ldsm4(uint32_t* r, uint32_t a) {
    asm volatile("ldmatrix.sync.aligned.m8n8.x4.shared.b16 {%0,%1,%2,%3}, [%4];"
        : "=r"(r[0]), "=r"(r[1]), "=r"(r[2]), "=r"(r[3]) : "r"(a));
}
__device__ __forceinline__ void ldsm4t(uint32_t* r, uint32_t a) {
    asm volatile("ldmatrix.sync.aligned.m8n8.x4.trans.shared.b16 {%0,%1,%2,%3}, [%4];"
        : "=r"(r[0]), "=r"(r[1]), "=r"(r[2]), "=r"(r[3]) : "r"(a));
}
__device__ __forceinline__ void mma16816(float* d, const uint32_t* a, const uint32_t* b) {
    asm volatile(
        "mma.sync.aligned.m16n8k16.row.col.f32.bf16.bf16.f32 "
        "{%0,%1,%2,%3}, {%4,%5,%6,%7}, {%8,%9}, {%0,%1,%2,%3};"
        : "+f"(d[0]), "+f"(d[1]), "+f"(d[2]), "+f"(d[3])
        : "r"(a[0]), "r"(a[1]), "r"(a[2]), "r"(a[3]), "r"(b[0]), "r"(b[1]));
}
__device__ __forceinline__ uint32_t pk_bf2(float lo, float hi) {
    uint32_t r;
    asm("cvt.rn.bf16x2.f32 %0, %1, %2;" : "=r"(r) : "f"(hi), "f"(lo));
    return r;
}

// =====================================================================
// Kernel 0: reorder+split Wc, split W2^T, precompute Ast
// =====================================================================
__global__ void k0_prep(const float* __restrict__ Wc, const float* __restrict__ W2,
                        const float* __restrict__ W1) {
    int i = blockIdx.x * 256 + threadIdx.x;
    if (i < COUT * KTOT) {
        int o = i >> 10, k = i & 1023;
        int c = k >> 4, pos = k & 15;
        int kp = pos * 64 + c;
        float v = Wc[i];
        __nv_bfloat16 h = __float2bfloat16(v);
        g_WcH[o * 1024 + kp] = h;
        g_WcL[o * 1024 + kp] = __float2bfloat16(v - __bfloat162float(h));
    }
    if (i < CIN * CIN) {
        int j = i >> 6, c = i & 63;
        float v = W2[i];
        __nv_bfloat16 h = __float2bfloat16(v);
        g_W2TH[c * 64 + j] = h;
        g_W2TL[c * 64 + j] = __float2bfloat16(v - __bfloat162float(h));
    }
    if (i < CIN * 16) {
        int j = i >> 4, pos = i & 15;
        int u = pos >> 2, v = pos & 3;
        float du = (float)(u - 2), dv = (float)(v - 2);
        float ca = cosf(AZI_C * dv), sa = sinf(AZI_C * dv);
        float ci = cosf(INC_C * du), si = sinf(INC_C * du);
        g_Ast[i] = ca * ci * W1[j] + ca * si * W1[64 + j] + sa * W1[128 + j];
    }
}

// =====================================================================
// Fused kernel v2: warp-private Wc streaming, no barriers in out-GEMM.
// grid (16, 32, 4), 256 threads, 1 CTA/SM.
// smem byte map:
//   0      : hs planes (H 32K | L 32K)  /  m [512 rows][128B SWA] (time-shared)
//   65536  : Wc warp-private stream: 8 warps x 2 stages x 4KB = 64K
//   131072 : xs f32 [64][264] (67584)
//   198656 : W2TH (8192) ; 206848 : W2TL (8192)
//   215040 : Ast (4096) ; 219136: W10 ; 219392: b1 ; 219648: b2
//   219904 : rs [4][66] (1056)  -> 220960 total
// =====================================================================
#define M_B     0
#define HSH_B   0
#define HSL_B   32768
#define WC_B    65536
#define XS_B    131072
#define W2TH_B  198656
#define W2TL_B  206848
#define AST_B   215040
#define W10_B   219136
#define B1_B    219392
#define B2_B    219648
#define RS_B    219904
#define SM1_BYTES 220960

__global__ void __launch_bounds__(256, 1)
k1_fused(const float* __restrict__ x, const float* __restrict__ r,
         const float* __restrict__ W1, const float* __restrict__ b1,
         const float* __restrict__ b2, const float* __restrict__ bc,
         float* __restrict__ out, float* __restrict__ rcout)
{
    extern __shared__ float sm[];
    float* xs   = sm + XS_B / 4;
    float* Ast  = sm + AST_B / 4;
    float* W10s = sm + W10_B / 4;
    float* b1s  = sm + B1_B / 4;
    float* b2s  = sm + B2_B / 4;
    float* rs   = sm + RS_B / 4;
    char*  smc  = (char*)sm;
    const uint32_t sb = smem_u32(sm);

    const int tid  = threadIdx.x;
    const int lane = tid & 31;
    const int wid  = tid >> 5;
    const int ho   = blockIdx.y;
    const int bz   = blockIdx.z;
    const int wo0  = blockIdx.x * 32;

    if (tid < 64) { W10s[tid] = W1[tid]; b1s[tid] = b1[tid]; b2s[tid] = b2[tid]; }
    for (int i = tid; i < 1024; i += 256) Ast[i] = g_Ast[i];
    for (int i = tid; i < 4 * 66; i += 256) {
        int v = i / 66, cc = i % 66;
        int rowp = 2 * ho + v;
        int row  = (rowp == 0) ? (HH - 1) : ((rowp == HH + 1) ? 0 : rowp - 1);
        int colp = 2 * wo0 + cc;
        float val;
        if (colp == 0 || colp == WW + 1) val = 100.0f;
        else val = r[((size_t)bz * HH + row) * WW + (colp - 1)];
        rs[i] = val;
    }
    for (int i = tid; i < 4096; i += 256) {
        int row = i >> 6, col = i & 63;
        uint32_t off = SWA(row * 128 + col * 2);
        *(__nv_bfloat16*)(smc + W2TH_B + off) = g_W2TH[i];
        *(__nv_bfloat16*)(smc + W2TL_B + off) = g_W2TL[i];
    }
    {   // xs staging, division-free
        int xr[4];
        #pragma unroll
        for (int v = 0; v < 4; v++) {
            int rowp = 2 * ho + v;
            xr[v] = (rowp == 0) ? (HH - 1) : ((rowp == HH + 1) ? 0 : rowp - 1);
        }
        const int gbase = 2 * wo0 - 1;
        #pragma unroll 4
        for (int it = 0; it < 64; it++) {
            int flat = tid + it * 256;
            int cc = flat & 63;
            int rv = flat >> 6;
            int c = rv >> 2, v = rv & 3;
            int g = gbase + cc;
            float val = 0.0f;
            if (g >= 0)
                val = x[(((size_t)(bz * CIN + c)) * HH + xr[v]) * WW + g];
            xs[c * 264 + v * 66 + cc] = val;
        }
        for (int it = 0; it < 2; it++) {
            int flat = tid + it * 256;
            int cc = 64 + (flat & 1);
            int rv = flat >> 1;
            int c = rv >> 2, v = rv & 3;
            int g = gbase + cc;
            float val = 0.0f;
            if (g < WW)
                val = x[(((size_t)(bz * CIN + c)) * HH + xr[v]) * WW + g];
            xs[c * 264 + v * 66 + cc] = val;
        }
    }

    float oacc[4][4];
    #pragma unroll
    for (int nt = 0; nt < 4; nt++)
        #pragma unroll
        for (int q = 0; q < 4; q++) oacc[nt][q] = 0.0f;

    // warp-private Wc chunk loader (4KB per chunk: 16 rows x 128B, H|L)
    const uint32_t wbuf = sb + WC_B + wid * 8192;
    auto load_wc = [&](int s, int ch) {
        const uint32_t stage = wbuf + (ch & 1) * 4096;
        const int k0 = s * 512 + ch * 64;
        #pragma unroll
        for (int p = 0; p < 8; p++) {
            int idx = lane + (p & 3) * 32;        // 0..127
            const __nv_bfloat16* W = (p < 4) ? g_WcH : g_WcL;
            int row = idx >> 3, un = idx & 7;
            uint32_t sa = stage + ((p < 4) ? 0 : 2048) + SWA(row * 128 + un * 16);
            cp16(sa, W + (size_t)(wid * 16 + row) * KTOT + k0 + un * 8);
        }
        CP_COMMIT();
    };

    const int wmg = (wid & 1) * 32;     // w-GEMM warp M (c)
    const int wng = (wid >> 1) * 64;    // w-GEMM warp N (combo)

    for (int s = 0; s < 2; s++) {
        // warp-private prefetch (safe pre-barrier: buffers are warp-owned)
        load_wc(s, 0);
        load_wc(s, 1);
        __syncthreads();   // covers: init staging (s=0); m readers done (s=1)

        // ---- h compute, shfl-paired bf16x2 split -> hs ----
        {
            int pos  = 8 * s + wid;
            int u = pos >> 2, v = pos & 3;
            int px = lane;
            float R   = rs[v * 66 + 2 * px + u];
            float nrc = -rs[2 * 66 + 2 * px + 2];
            const uint32_t plane = (lane & 1) ? (sb + HSL_B) : (sb + HSH_B);
            const int wordb = (tid & ~1) * 2;
            #pragma unroll 8
            for (int j = 0; j < 64; j++) {
                float t = fmaf(R, Ast[j * 16 + pos], fmaf(nrc, W10s[j], b1s[j]));
                t = (t > 0.0f) ? t : 0.2f * t;
                __nv_bfloat16 hb = __float2bfloat16(t);
                float rem = t - __bfloat162float(hb);
                float t_o   = __shfl_xor_sync(0xffffffffu, t, 1);
                float rem_o = __shfl_xor_sync(0xffffffffu, rem, 1);
                uint32_t wH = pk_bf2(t, t_o);
                uint32_t wL = pk_bf2(rem_o, rem);
                uint32_t word = (lane & 1) ? wL : wH;
                sts32(plane + SWC(j * 512 + wordb), word);
            }
        }
        __syncthreads();

        // ---- w-GEMM into registers ----
        float acc[2][8][4];
        #pragma unroll
        for (int mi = 0; mi < 2; mi++)
            #pragma unroll
            for (int nt = 0; nt < 8; nt++)
                #pragma unroll
                for (int q = 0; q < 4; q++) acc[mi][nt][q] = 0.0f;

        #pragma unroll
        for (int ks = 0; ks < 4; ks++) {
            uint32_t aH[2][4], aL[2][4];
            int arow  = wmg + (lane & 15);
            int acolb = ks * 32 + ((lane >> 4) << 4);
            #pragma unroll
            for (int mi = 0; mi < 2; mi++) {
                uint32_t off = SWA((arow + mi * 16) * 128 + acolb);
                ldsm4(aH[mi], sb + W2TH_B + off);
                ldsm4(aL[mi], sb + W2TL_B + off);
            }
            int browb = (ks * 16 + (lane & 15)) * 512;
            #pragma unroll
            for (int g = 0; g < 4; g++) {
                uint32_t off = SWC(browb + wng * 2 + g * 32 + ((lane >> 4) << 4));
                uint32_t bh[4], bl[4];
                ldsm4t(bh, sb + HSH_B + off);
                ldsm4t(bl, sb + HSL_B + off);
                #pragma unroll
                for (int mi = 0; mi < 2; mi++) {
                    mma16816(acc[mi][2*g],   aH[mi], bh);
                    mma16816(acc[mi][2*g+1], aH[mi], bh + 2);
                    mma16816(acc[mi][2*g],   aL[mi], bh);
                    mma16816(acc[mi][2*g+1], aL[mi], bh + 2);
                    mma16816(acc[mi][2*g],   aH[mi], bl);
                    mma16816(acc[mi][2*g+1], aH[mi], bl + 2);
                }
            }
        }
        __syncthreads();   // hs consumed; reuse region as m

        // ---- phase B: m = (acc+b2)*x -> m smem (512 rows x 128B, SWA) ----
        #pragma unroll
        for (int mi = 0; mi < 2; mi++) {
            int r0 = wmg + mi * 16 + (lane >> 2);
            int r2 = r0 + 8;
            float b2a = b2s[r0], b2b = b2s[r2];
            #pragma unroll 2
            for (int nt = 0; nt < 8; nt++) {
                int col0 = wng + nt * 8 + (lane & 3) * 2;
                int posl = col0 >> 5;
                int px0  = col0 & 31;
                int pos  = 8 * s + posl;
                int u = pos >> 2, v = pos & 3;
                const float* xr0 = xs + r0 * 264 + v * 66 + u;
                const float* xr2 = xs + r2 * 264 + v * 66 + u;
                float m0 = (acc[mi][nt][0] + b2a) * xr0[2 * px0];
                float m1 = (acc[mi][nt][1] + b2a) * xr0[2 * px0 + 2];
                float m2 = (acc[mi][nt][2] + b2b) * xr2[2 * px0];
                float m3 = (acc[mi][nt][3] + b2b) * xr2[2 * px0 + 2];
                float l0 = m0 - __bfloat162float(__float2bfloat16(m0));
                float l1 = m1 - __bfloat162float(__float2bfloat16(m1));
                float l2 = m2 - __bfloat162float(__float2bfloat16(m2));
                float l3 = m3 - __bfloat162float(__float2bfloat16(m3));
                uint32_t rowa = (uint32_t)(posl * 64 + r0) * 128;
                uint32_t rowb = (uint32_t)(posl * 64 + r2) * 128;
                sts32(sb + M_B + SWA(rowa + 2 * px0),      pk_bf2(m0, m1));
                sts32(sb + M_B + SWA(rowa + 64 + 2 * px0), pk_bf2(l0, l1));
                sts32(sb + M_B + SWA(rowb + 2 * px0),      pk_bf2(m2, m3));
                sts32(sb + M_B + SWA(rowb + 64 + 2 * px0), pk_bf2(l2, l3));
            }
        }
        __syncthreads();   // m fully written; out-GEMM reads it barrier-free

        // ---- out-GEMM: 8 chunks, warp-private A stream, NO block barriers ----
        for (int ch = 0; ch < 8; ch++) {
            if (ch == 7) { CP_WAIT0(); } else { CP_WAIT1(); }
            __syncwarp();
            const uint32_t stH = wbuf + (ch & 1) * 4096;
            const uint32_t stL = stH + 2048;
            #pragma unroll
            for (int ks = 0; ks < 4; ks++) {
                uint32_t aH[4], aL[4];
                int arow  = lane & 15;
                int acolb = ks * 32 + ((lane >> 4) << 4);
                uint32_t aoff = SWA(arow * 128 + acolb);
                ldsm4(aH, stH + aoff);
                ldsm4(aL, stL + aoff);
                int brow = ch * 64 + ks * 16 + (lane & 15);
                #pragma unroll
                for (int g = 0; g < 2; g++) {
                    int nb = (g * 16 + ((lane >> 4) << 3)) * 2;
                    uint32_t bh[4], bl[4];
                    ldsm4t(bh, sb + M_B + SWA(brow * 128 + nb));
                    ldsm4t(bl, sb + M_B + SWA(brow * 128 + 64 + nb));
                    mma16816(oacc[2*g],   aH, bh);
                    mma16816(oacc[2*g+1], aH, bh + 2);
                    mma16816(oacc[2*g],   aL, bh);
                    mma16816(oacc[2*g+1], aL, bh + 2);
                    mma16816(oacc[2*g],   aH, bl);
                    mma16816(oacc[2*g+1], aH, bl + 2);
                }
            }
            if (ch + 2 < 8) load_wc(s, ch + 2);
        }
    }

    // ---- epilogue: bias + store out ----
    {
        const size_t base = (size_t)bz * (COUT * 16384) + (size_t)ho * 512 + wo0;
        int r0 = wid * 16 + (lane >> 2);
        float bv0 = bc[r0], bv1 = bc[r0 + 8];
        float* row0 = out + base + (size_t)r0 * 16384;
        float* row1 = out + base + (size_t)(r0 + 8) * 16384;
        #pragma unroll
        for (int nt = 0; nt < 4; nt++) {
            int col = nt * 8 + (lane & 3) * 2;
            float2 v0, v1;
            v0.x = oacc[nt][0] + bv0; v0.y = oacc[nt][1] + bv0;
            v1.x = oacc[nt][2] + bv1; v1.y = oacc[nt][3] + bv1;
            *(float2*)(row0 + col) = v0;
            *(float2*)(row1 + col) = v1;
        }
    }

    if (rcout != nullptr && tid < 32) {
        rcout[(size_t)bz * 16384 + (size_t)ho * 512 + wo0 + tid] =
            rs[2 * 66 + 2 * tid + 2];
    }
}

extern "C" void kernel_launch(void* const* d_in, const int* in_sizes, int n_in,
                              void* d_out, int out_size) {
    const float* x  = (const float*)d_in[0];
    const float* r  = (const float*)d_in[1];
    const float* W1 = (const float*)d_in[2];
    const float* b1 = (const float*)d_in[3];
    const float* W2 = (const float*)d_in[4];
    const float* b2 = (const float*)d_in[5];
    const float* Wc = (const float*)d_in[6];
    const float* bc = (const float*)d_in[7];
    float* out = (float*)d_out;

    cudaFuncSetAttribute(k1_fused, cudaFuncAttributeMaxDynamicSharedMemorySize, SM1_BYTES);

    float* rcout = (out_size > OUT0) ? (out + OUT0) : nullptr;

    k0_prep<<<(COUT * KTOT + 255) / 256, 256>>>(Wc, W2, W1);
    dim3 g1(16, 32, 4);
    k1_fused<<<g1, 256, SM1_BYTES>>>(x, r, W1, b1, b2, bc, out, rcout);
}

// round 10
// speedup vs baseline: 1.1854x; 1.1854x over previous
#include <cuda_runtime.h>
#include <cuda_bf16.h>
#include <cstdint>
#include <cstddef>

#define BATCH   4
#define CIN     64
#define COUT    128
#define HH      64
#define WW      1024
#define HO      32
#define WO      512
#define NPIX    65536
#define KTOT    1024
#define OUT0    8388608
#define AZI_C   0.006135923151542565f
#define INC_C   0.0073f

__device__ __nv_bfloat16 g_mh[(size_t)KTOT * NPIX];
__device__ __nv_bfloat16 g_ml[(size_t)KTOT * NPIX];
__device__ __nv_bfloat16 g_WcH[COUT * KTOT];
__device__ __nv_bfloat16 g_WcL[COUT * KTOT];
__device__ __nv_bfloat16 g_W2TH[CIN * CIN];   // [c][j]
__device__ __nv_bfloat16 g_W2TL[CIN * CIN];
__device__ float g_Ast[CIN * 16];             // [j][pos]

__device__ __forceinline__ uint32_t smem_u32(const void* p) {
    uint32_t a;
    asm("{ .reg .u64 t; cvta.to.shared.u64 t, %1; cvt.u32.u64 %0, t; }" : "=r"(a) : "l"(p));
    return a;
}
#define SWA(o) ((o) ^ (((o) >> 3) & 0x70))
#define SWC(o) ((o) ^ (((o) >> 5) & 0x70))

__device__ __forceinline__ void sts32(uint32_t saddr, uint32_t v) {
    asm volatile("st.shared.u32 [%0], %1;" :: "r"(saddr), "r"(v) : "memory");
}
__device__ __forceinline__ void cp16(uint32_t saddr, const void* gaddr) {
    asm volatile("cp.async.cg.shared.global [%0], [%1], 16;" :: "r"(saddr), "l"(gaddr));
}
#define CP_COMMIT() asm volatile("cp.async.commit_group;" ::: "memory")
#define CP_WAIT1()  asm volatile("cp.async.wait_group 1;" ::: "memory")
#define CP_WAIT0()  asm volatile("cp.async.wait_group 0;" ::: "memory")

__device__ __forceinline__ void ldsm4(uint32_t* r, uint32_t a) {
    asm volatile("ldmatrix.sync.aligned.m8n8.x4.shared.b16 {%0,%1,%2,%3}, [%4];"
        : "=r"(r[0]), "=r"(r[1]), "=r"(r[2]), "=r"(r[3]) : "r"(a));
}
__device__ __forceinline__ void ldsm4t(uint32_t* r, uint32_t a) {
    asm volatile("ldmatrix.sync.aligned.m8n8.x4.trans.shared.b16 {%0,%1,%2,%3}, [%4];"
        : "=r"(r[0]), "=r"(r[1]), "=r"(r[2]), "=r"(r[3]) : "r"(a));
}
__device__ __forceinline__ void mma16816(float* d, const uint32_t* a, const uint32_t* b) {
    asm volatile(
        "mma.sync.aligned.m16n8k16.row.col.f32.bf16.bf16.f32 "
        "{%0,%1,%2,%3}, {%4,%5,%6,%7}, {%8,%9}, {%0,%1,%2,%3};"
        : "+f"(d[0]), "+f"(d[1]), "+f"(d[2]), "+f"(d[3])
        : "r"(a[0]), "r"(a[1]), "r"(a[2]), "r"(a[3]), "r"(b[0]), "r"(b[1]));
}
__device__ __forceinline__ uint32_t pk_bf2(float lo, float hi) {
    uint32_t r;
    asm("cvt.rn.bf16x2.f32 %0, %1, %2;" : "=r"(r) : "f"(hi), "f"(lo));
    return r;
}

// =====================================================================
// Kernel 0: split Wc + W2^T into bf16 hi/lo, precompute Ast (R7 form)
// =====================================================================
__global__ void k0_prep(const float* __restrict__ Wc, const float* __restrict__ W2,
                        const float* __restrict__ W1) {
    int i = blockIdx.x * 256 + threadIdx.x;
    if (i < COUT * KTOT) {
        float v = Wc[i];
        __nv_bfloat16 h = __float2bfloat16(v);
        g_WcH[i] = h;
        g_WcL[i] = __float2bfloat16(v - __bfloat162float(h));
    }
    if (i < CIN * CIN) {
        int j = i >> 6, c = i & 63;
        float v = W2[i];
        __nv_bfloat16 h = __float2bfloat16(v);
        g_W2TH[c * 64 + j] = h;
        g_W2TL[c * 64 + j] = __float2bfloat16(v - __bfloat162float(h));
    }
    if (i < CIN * 16) {
        int j = i >> 4, pos = i & 15;
        int u = pos >> 2, v = pos & 3;
        float du = (float)(u - 2), dv = (float)(v - 2);
        float ca = cosf(AZI_C * dv), sa = sinf(AZI_C * dv);
        float ci = cosf(INC_C * du), si = sinf(INC_C * du);
        g_Ast[i] = ca * ci * W1[j] + ca * si * W1[64 + j] + sa * W1[128 + j];
    }
}

// =====================================================================
// Kernel 1: identical to R7 (known 383us, rel_err 7.45e-6)
// =====================================================================
#define WS_F    0
#define XS_F    16640
#define HSH_B   134144
#define HSL_B   166912
#define W2TH_B  199680
#define W2TL_B  207872
#define AST_F   54016
#define W10_F   55040
#define B1_F    55104
#define B2_F    55168
#define RS_F    55232
#define SM1_BYTES 221984

__global__ void __launch_bounds__(256, 1)
k1_weights(const float* __restrict__ x, const float* __restrict__ r,
           const float* __restrict__ W1, const float* __restrict__ b1,
           const float* __restrict__ b2, float* __restrict__ rcout)
{
    extern __shared__ float sm[];
    float* ws   = sm + WS_F;     // f32 [64][260]
    float* xs   = sm + XS_F;     // f32 [64][264]
    float* Ast  = sm + AST_F;
    float* W10s = sm + W10_F;
    float* b1s  = sm + B1_F;
    float* b2s  = sm + B2_F;
    float* rs   = sm + RS_F;
    char*  smc  = (char*)sm;
    const uint32_t sb = smem_u32(sm);

    const int tid  = threadIdx.x;
    const int lane = tid & 31;
    const int wid  = tid >> 5;
    const int ho   = blockIdx.y;
    const int bz   = blockIdx.z;
    const int wo0  = blockIdx.x * 32;

    if (tid < 64) { W10s[tid] = W1[tid]; b1s[tid] = b1[tid]; b2s[tid] = b2[tid]; }
    for (int i = tid; i < 1024; i += 256) Ast[i] = g_Ast[i];
    for (int i = tid; i < 4 * 66; i += 256) {
        int v = i / 66, cc = i % 66;
        int rowp = 2 * ho + v;
        int row  = (rowp == 0) ? (HH - 1) : ((rowp == HH + 1) ? 0 : rowp - 1);
        int colp = 2 * wo0 + cc;
        float val;
        if (colp == 0 || colp == WW + 1) val = 100.0f;
        else val = r[((size_t)bz * HH + row) * WW + (colp - 1)];
        rs[i] = val;
    }
    for (int i = tid; i < 4096; i += 256) {
        int row = i >> 6, col = i & 63;
        uint32_t off = SWA(row * 128 + col * 2);
        *(__nv_bfloat16*)(smc + W2TH_B + off) = g_W2TH[i];
        *(__nv_bfloat16*)(smc + W2TL_B + off) = g_W2TL[i];
    }
    {
        int xr[4];
        #pragma unroll
        for (int v = 0; v < 4; v++) {
            int rowp = 2 * ho + v;
            xr[v] = (rowp == 0) ? (HH - 1) : ((rowp == HH + 1) ? 0 : rowp - 1);
        }
        const int gbase = 2 * wo0 - 1;
        #pragma unroll 4
        for (int it = 0; it < 64; it++) {
            int flat = tid + it * 256;
            int cc = flat & 63;
            int rv = flat >> 6;
            int c = rv >> 2, v = rv & 3;
            int g = gbase + cc;
            float val = 0.0f;
            if (g >= 0)
                val = x[(((size_t)(bz * CIN + c)) * HH + xr[v]) * WW + g];
            xs[c * 264 + v * 66 + cc] = val;
        }
        for (int it = 0; it < 2; it++) {
            int flat = tid + it * 256;
            int cc = 64 + (flat & 1);
            int rv = flat >> 1;
            int c = rv >> 2, v = rv & 3;
            int g = gbase + cc;
            float val = 0.0f;
            if (g < WW)
                val = x[(((size_t)(bz * CIN + c)) * HH + xr[v]) * WW + g];
            xs[c * 264 + v * 66 + cc] = val;
        }
    }
    __syncthreads();

    const size_t nbase = (size_t)bz * 16384 + (size_t)ho * 512 + wo0;
    const int wm = (wid & 1) * 32;
    const int wn = (wid >> 1) * 64;

    for (int s = 0; s < 2; s++) {
        {
            int pos  = 8 * s + wid;
            int u = pos >> 2, v = pos & 3;
            int px = lane;
            float R   = rs[v * 66 + 2 * px + u];
            float nrc = -rs[2 * 66 + 2 * px + 2];
            const uint32_t plane = (lane & 1) ? (sb + HSL_B) : (sb + HSH_B);
            const int wordb = (tid & ~1) * 2;
            #pragma unroll 8
            for (int j = 0; j < 64; j++) {
                float t = fmaf(R, Ast[j * 16 + pos], fmaf(nrc, W10s[j], b1s[j]));
                t = (t > 0.0f) ? t : 0.2f * t;
                __nv_bfloat16 hb = __float2bfloat16(t);
                float rem = t - __bfloat162float(hb);
                float t_o   = __shfl_xor_sync(0xffffffffu, t, 1);
                float rem_o = __shfl_xor_sync(0xffffffffu, rem, 1);
                uint32_t wH = pk_bf2(t, t_o);
                uint32_t wL = pk_bf2(rem_o, rem);
                uint32_t word = (lane & 1) ? wL : wH;
                sts32(plane + SWC(j * 512 + wordb), word);
            }
        }
        __syncthreads();

        {
            float acc[2][8][4];
            #pragma unroll
            for (int mi = 0; mi < 2; mi++)
                #pragma unroll
                for (int nt = 0; nt < 8; nt++)
                    #pragma unroll
                    for (int q = 0; q < 4; q++) acc[mi][nt][q] = 0.0f;

            #pragma unroll
            for (int ks = 0; ks < 4; ks++) {
                uint32_t aH[2][4], aL[2][4];
                int arow  = wm + (lane & 15);
                int acolb = ks * 32 + ((lane >> 4) << 4);
                #pragma unroll
                for (int mi = 0; mi < 2; mi++) {
                    uint32_t off = SWA((arow + mi * 16) * 128 + acolb);
                    ldsm4(aH[mi], sb + W2TH_B + off);
                    ldsm4(aL[mi], sb + W2TL_B + off);
                }
                int browb = (ks * 16 + (lane & 15)) * 512;
                #pragma unroll
                for (int g = 0; g < 4; g++) {
                    uint32_t off = SWC(browb + wn * 2 + g * 32 + ((lane >> 4) << 4));
                    uint32_t bh[4], bl[4];
                    ldsm4t(bh, sb + HSH_B + off);
                    ldsm4t(bl, sb + HSL_B + off);
                    #pragma unroll
                    for (int mi = 0; mi < 2; mi++) {
                        mma16816(acc[mi][2*g],   aH[mi], bh);
                        mma16816(acc[mi][2*g+1], aH[mi], bh + 2);
                        mma16816(acc[mi][2*g],   aL[mi], bh);
                        mma16816(acc[mi][2*g+1], aL[mi], bh + 2);
                        mma16816(acc[mi][2*g],   aH[mi], bl);
                        mma16816(acc[mi][2*g+1], aH[mi], bl + 2);
                    }
                }
            }

            #pragma unroll
            for (int mi = 0; mi < 2; mi++) {
                int r0 = wm + mi * 16 + (lane >> 2);
                float b2a = b2s[r0], b2b = b2s[r0 + 8];
                #pragma unroll
                for (int nt = 0; nt < 8; nt++) {
                    int col = wn + nt * 8 + (lane & 3) * 2;
                    float2 v0, v1;
                    v0.x = acc[mi][nt][0] + b2a; v0.y = acc[mi][nt][1] + b2a;
                    v1.x = acc[mi][nt][2] + b2b; v1.y = acc[mi][nt][3] + b2b;
                    *(float2*)(ws + r0 * 260 + col) = v0;
                    *(float2*)(ws + (r0 + 8) * 260 + col) = v1;
                }
            }
        }
        __syncthreads();

        {
            int posl = wid;
            int pos  = 8 * s + posl;
            int u = pos >> 2, v = pos & 3;
            int px = lane;
            const float* xrow = xs + v * 66 + 2 * px + u;
            const float* wsr  = ws + posl * 32 + px;
            __nv_bfloat16* gmh = g_mh + (size_t)pos * NPIX + nbase + px;
            __nv_bfloat16* gml = g_ml + (size_t)pos * NPIX + nbase + px;
            #pragma unroll 8
            for (int c = 0; c < 64; c++) {
                float wv = wsr[c * 260];
                float xv = xrow[c * 264];
                float mv = wv * xv;
                __nv_bfloat16 hi = __float2bfloat16(mv);
                float rem = mv - __bfloat162float(hi);
                gmh[(size_t)c * 16 * NPIX] = hi;
                gml[(size_t)c * 16 * NPIX] = __float2bfloat16(rem);
            }
        }
        __syncthreads();
    }

    if (rcout != nullptr && tid < 32) {
        rcout[nbase + tid] = rs[2 * 66 + 2 * tid + 2];
    }
}

// =====================================================================
// Kernel 2 v2: HMMA bf16 split GEMM, 512 threads, N-tile 256.
// 16 warps (4 o-groups x 4 n-groups), stage 96KB x2, grid 256.
// Stage: Ah 16K | Al 16K | Bh 32K | Bl 32K. A rows 128B SWA; B rows 512B SWC.
// =====================================================================
#define K2_STAGE 98304
#define K2_SMEM  (2 * K2_STAGE)

__global__ void __launch_bounds__(512, 1)
k2_hmma(const float* __restrict__ bc, float* __restrict__ out)
{
    extern __shared__ char sm2[];
    const uint32_t sb = smem_u32(sm2);
    const int tid  = threadIdx.x;
    const int wid  = tid >> 5;
    const int lane = tid & 31;
    const int n0 = blockIdx.x * 256;
    const int wm = (wid & 3) * 32;      // o offset
    const int wn = (wid >> 2) * 64;     // n offset

    float acc[2][8][4];
    #pragma unroll
    for (int mi = 0; mi < 2; mi++)
        #pragma unroll
        for (int nt = 0; nt < 8; nt++)
            #pragma unroll
            for (int q = 0; q < 4; q++) acc[mi][nt][q] = 0.0f;

    auto load_chunk = [&](int c, int s) {
        const uint32_t base = sb + s * K2_STAGE;
        const int k0 = c * 64;
        // A: 2048 16B units (Ah 1024 + Al 1024)
        #pragma unroll
        for (int t = 0; t < 4; t++) {
            int ci = tid + (t & 1) * 512;           // 0..1023
            const __nv_bfloat16* W = (t < 2) ? g_WcH : g_WcL;
            int row = ci >> 3, un = ci & 7;
            uint32_t sa = base + ((t < 2) ? 0 : 16384) + SWA(row * 128 + un * 16);
            cp16(sa, W + (size_t)row * KTOT + k0 + un * 8);
        }
        // B: 4096 units (Bh 2048 + Bl 2048), rows 512B
        #pragma unroll
        for (int t = 0; t < 8; t++) {
            int ci = tid + (t & 3) * 512;           // 0..2047
            const __nv_bfloat16* M = (t < 4) ? g_mh : g_ml;
            int row = ci >> 5, un = ci & 31;
            uint32_t sa = base + ((t < 4) ? 32768 : 65536) + SWC(row * 512 + un * 16);
            cp16(sa, M + (size_t)(k0 + row) * NPIX + n0 + un * 8);
        }
        CP_COMMIT();
    };

    load_chunk(0, 0);
    load_chunk(1, 1);

    for (int c = 0; c < 16; c++) {
        const int s = c & 1;
        if (c == 15) { CP_WAIT0(); } else { CP_WAIT1(); }
        __syncthreads();

        const uint32_t bAh = sb + s * K2_STAGE;
        const uint32_t bAl = bAh + 16384;
        const uint32_t bBh = bAh + 32768;
        const uint32_t bBl = bAh + 65536;

        #pragma unroll
        for (int ks = 0; ks < 4; ks++) {
            uint32_t a_h[2][4], a_l[2][4];
            {
                int arow  = wm + (lane & 15);
                int acolb = ks * 32 + ((lane >> 4) << 4);
                #pragma unroll
                for (int mi = 0; mi < 2; mi++) {
                    uint32_t off = SWA((arow + mi * 16) * 128 + acolb);
                    ldsm4(a_h[mi], bAh + off);
                    ldsm4(a_l[mi], bAl + off);
                }
            }
            int browb = (ks * 16 + (lane & 15)) * 512;
            #pragma unroll
            for (int g = 0; g < 4; g++) {
                uint32_t off = SWC(browb + (wn + g * 16 + ((lane >> 4) << 3)) * 2);
                uint32_t bh[4], bl[4];
                ldsm4t(bh, bBh + off);
                ldsm4t(bl, bBl + off);
                #pragma unroll
                for (int mi = 0; mi < 2; mi++) {
                    mma16816(acc[mi][2*g],   a_h[mi], bh);
                    mma16816(acc[mi][2*g+1], a_h[mi], bh + 2);
                    mma16816(acc[mi][2*g],   a_l[mi], bh);
                    mma16816(acc[mi][2*g+1], a_l[mi], bh + 2);
                    mma16816(acc[mi][2*g],   a_h[mi], bl);
                    mma16816(acc[mi][2*g+1], a_h[mi], bl + 2);
                }
            }
        }
        __syncthreads();
        if (c + 2 < 16) load_chunk(c + 2, s);
    }

    const int bz = n0 >> 14;
    const int ncb = n0 & 16383;
    #pragma unroll
    for (int mi = 0; mi < 2; mi++) {
        int r0 = wm + mi * 16 + (lane >> 2);
        float bv0 = bc[r0], bv1 = bc[r0 + 8];
        float* row0 = out + ((size_t)(bz * COUT + r0))     * 16384 + ncb;
        float* row1 = out + ((size_t)(bz * COUT + r0 + 8)) * 16384 + ncb;
        #pragma unroll
        for (int nt = 0; nt < 8; nt++) {
            int col = wn + nt * 8 + (lane & 3) * 2;
            float2 v0, v1;
            v0.x = acc[mi][nt][0] + bv0; v0.y = acc[mi][nt][1] + bv0;
            v1.x = acc[mi][nt][2] + bv1; v1.y = acc[mi][nt][3] + bv1;
            *(float2*)(row0 + col) = v0;
            *(float2*)(row1 + col) = v1;
        }
    }
}

extern "C" void kernel_launch(void* const* d_in, const int* in_sizes, int n_in,
                              void* d_out, int out_size) {
    const float* x  = (const float*)d_in[0];
    const float* r  = (const float*)d_in[1];
    const float* W1 = (const float*)d_in[2];
    const float* b1 = (const float*)d_in[3];
    const float* W2 = (const float*)d_in[4];
    const float* b2 = (const float*)d_in[5];
    const float* Wc = (const float*)d_in[6];
    const float* bc = (const float*)d_in[7];
    float* out = (float*)d_out;

    cudaFuncSetAttribute(k1_weights, cudaFuncAttributeMaxDynamicSharedMemorySize, SM1_BYTES);
    cudaFuncSetAttribute(k2_hmma, cudaFuncAttributeMaxDynamicSharedMemorySize, K2_SMEM);

    float* rcout = (out_size > OUT0) ? (out + OUT0) : nullptr;

    k0_prep<<<(COUT * KTOT + 255) / 256, 256>>>(Wc, W2, W1);
    dim3 g1(16, 32, 4);
    k1_weights<<<g1, 256, SM1_BYTES>>>(x, r, W1, b1, b2, rcout);
    k2_hmma<<<256, 512, K2_SMEM>>>(bc, out);
}

// round 11
// speedup vs baseline: 1.5617x; 1.3174x over previous
#include <cuda_runtime.h>
#include <cuda_bf16.h>
#include <cstdint>
#include <cstddef>

#define BATCH   4
#define CIN     64
#define COUT    128
#define HH      64
#define WW      1024
#define HO      32
#define WO      512
#define NPIX    65536
#define KTOT    1024
#define OUT0    8388608
#define AZI_C   0.006135923151542565f
#define INC_C   0.0073f

__device__ __nv_bfloat16 g_mh[(size_t)KTOT * NPIX];
__device__ __nv_bfloat16 g_ml[(size_t)KTOT * NPIX];
__device__ __nv_bfloat16 g_WcH[COUT * KTOT];
__device__ __nv_bfloat16 g_WcL[COUT * KTOT];
__device__ __nv_bfloat16 g_W2TH[CIN * CIN];   // [c][j]
__device__ __nv_bfloat16 g_W2TL[CIN * CIN];
__device__ float g_Ast[CIN * 16];             // [j][pos]

__device__ __forceinline__ uint32_t smem_u32(const void* p) {
    uint32_t a;
    asm("{ .reg .u64 t; cvta.to.shared.u64 t, %1; cvt.u32.u64 %0, t; }" : "=r"(a) : "l"(p));
    return a;
}
#define SWA(o) ((o) ^ (((o) >> 3) & 0x70))
#define SWC(o) ((o) ^ (((o) >> 5) & 0x70))

__device__ __forceinline__ void sts32(uint32_t saddr, uint32_t v) {
    asm volatile("st.shared.u32 [%0], %1;" :: "r"(saddr), "r"(v) : "memory");
}
__device__ __forceinline__ void cp16(uint32_t saddr, const void* gaddr) {
    asm volatile("cp.async.cg.shared.global [%0], [%1], 16;" :: "r"(saddr), "l"(gaddr));
}
#define CP_COMMIT() asm volatile("cp.async.commit_group;" ::: "memory")
#define CP_WAIT1()  asm volatile("cp.async.wait_group 1;" ::: "memory")
#define CP_WAIT0()  asm volatile("cp.async.wait_group 0;" ::: "memory")

__device__ __forceinline__ void ldsm4(uint32_t* r, uint32_t a) {
    asm volatile("ldmatrix.sync.aligned.m8n8.x4.shared.b16 {%0,%1,%2,%3}, [%4];"
        : "=r"(r[0]), "=r"(r[1]), "=r"(r[2]), "=r"(r[3]) : "r"(a));
}
__device__ __forceinline__ void ldsm4t(uint32_t* r, uint32_t a) {
    asm volatile("ldmatrix.sync.aligned.m8n8.x4.trans.shared.b16 {%0,%1,%2,%3}, [%4];"
        : "=r"(r[0]), "=r"(r[1]), "=r"(r[2]), "=r"(r[3]) : "r"(a));
}
__device__ __forceinline__ void mma16816(float* d, const uint32_t* a, const uint32_t* b) {
    asm volatile(
        "mma.sync.aligned.m16n8k16.row.col.f32.bf16.bf16.f32 "
        "{%0,%1,%2,%3}, {%4,%5,%6,%7}, {%8,%9}, {%0,%1,%2,%3};"
        : "+f"(d[0]), "+f"(d[1]), "+f"(d[2]), "+f"(d[3])
        : "r"(a[0]), "r"(a[1]), "r"(a[2]), "r"(a[3]), "r"(b[0]), "r"(b[1]));
}
__device__ __forceinline__ uint32_t pk_bf2(float lo, float hi) {
    uint32_t r;
    asm("cvt.rn.bf16x2.f32 %0, %1, %2;" : "=r"(r) : "f"(hi), "f"(lo));
    return r;
}

// =====================================================================
// Kernel 0: split Wc + W2^T into bf16 hi/lo, precompute Ast
// =====================================================================
__global__ void k0_prep(const float* __restrict__ Wc, const float* __restrict__ W2,
                        const float* __restrict__ W1) {
    int i = blockIdx.x * 256 + threadIdx.x;
    if (i < COUT * KTOT) {
        float v = Wc[i];
        __nv_bfloat16 h = __float2bfloat16(v);
        g_WcH[i] = h;
        g_WcL[i] = __float2bfloat16(v - __bfloat162float(h));
    }
    if (i < CIN * CIN) {
        int j = i >> 6, c = i & 63;
        float v = W2[i];
        __nv_bfloat16 h = __float2bfloat16(v);
        g_W2TH[c * 64 + j] = h;
        g_W2TL[c * 64 + j] = __float2bfloat16(v - __bfloat162float(h));
    }
    if (i < CIN * 16) {
        int j = i >> 4, pos = i & 15;
        int u = pos >> 2, v = pos & 3;
        float du = (float)(u - 2), dv = (float)(v - 2);
        float ca = cosf(AZI_C * dv), sa = sinf(AZI_C * dv);
        float ci = cosf(INC_C * du), si = sinf(INC_C * du);
        g_Ast[i] = ca * ci * W1[j] + ca * si * W1[64 + j] + sa * W1[128 + j];
    }
}

// =====================================================================
// Kernel 1 v3: same algorithm/layouts as R7, 512 threads (4 warps/SMSP).
// grid (16, 32, 4), 1 CTA/SM.
// =====================================================================
#define WS_F    0
#define XS_F    16640
#define HSH_B   134144
#define HSL_B   166912
#define W2TH_B  199680
#define W2TL_B  207872
#define AST_F   54016
#define W10_F   55040
#define B1_F    55104
#define B2_F    55168
#define RS_F    55232
#define SM1_BYTES 221984

__global__ void __launch_bounds__(512, 1)
k1_weights(const float* __restrict__ x, const float* __restrict__ r,
           const float* __restrict__ W1, const float* __restrict__ b1,
           const float* __restrict__ b2, float* __restrict__ rcout)
{
    extern __shared__ float sm[];
    float* ws   = sm + WS_F;     // f32 [64][260]
    float* xs   = sm + XS_F;     // f32 [64][264]
    float* Ast  = sm + AST_F;
    float* W10s = sm + W10_F;
    float* b1s  = sm + B1_F;
    float* b2s  = sm + B2_F;
    float* rs   = sm + RS_F;
    char*  smc  = (char*)sm;
    const uint32_t sb = smem_u32(sm);

    const int tid  = threadIdx.x;
    const int lane = tid & 31;
    const int wid  = tid >> 5;          // 0..15
    const int ho   = blockIdx.y;
    const int bz   = blockIdx.z;
    const int wo0  = blockIdx.x * 32;

    if (tid < 64) { W10s[tid] = W1[tid]; b1s[tid] = b1[tid]; b2s[tid] = b2[tid]; }
    for (int i = tid; i < 1024; i += 512) Ast[i] = g_Ast[i];
    for (int i = tid; i < 4 * 66; i += 512) {
        int v = i / 66, cc = i % 66;
        int rowp = 2 * ho + v;
        int row  = (rowp == 0) ? (HH - 1) : ((rowp == HH + 1) ? 0 : rowp - 1);
        int colp = 2 * wo0 + cc;
        float val;
        if (colp == 0 || colp == WW + 1) val = 100.0f;
        else val = r[((size_t)bz * HH + row) * WW + (colp - 1)];
        rs[i] = val;
    }
    for (int i = tid; i < 4096; i += 512) {
        int row = i >> 6, col = i & 63;
        uint32_t off = SWA(row * 128 + col * 2);
        *(__nv_bfloat16*)(smc + W2TH_B + off) = g_W2TH[i];
        *(__nv_bfloat16*)(smc + W2TL_B + off) = g_W2TL[i];
    }
    {   // xs staging, division-free (512-thread stride)
        int xr[4];
        #pragma unroll
        for (int v = 0; v < 4; v++) {
            int rowp = 2 * ho + v;
            xr[v] = (rowp == 0) ? (HH - 1) : ((rowp == HH + 1) ? 0 : rowp - 1);
        }
        const int gbase = 2 * wo0 - 1;
        #pragma unroll 4
        for (int it = 0; it < 32; it++) {
            int flat = tid + it * 512;
            int cc = flat & 63;
            int rv = flat >> 6;
            int c = rv >> 2, v = rv & 3;
            int g = gbase + cc;
            float val = 0.0f;
            if (g >= 0)
                val = x[(((size_t)(bz * CIN + c)) * HH + xr[v]) * WW + g];
            xs[c * 264 + v * 66 + cc] = val;
        }
        if (tid < 512) {   // edge cc in {64,65}: 512 items
            int cc = 64 + (tid & 1);
            int rv = tid >> 1;
            int c = rv >> 2, v = rv & 3;
            int g = gbase + cc;
            float val = 0.0f;
            if (g < WW)
                val = x[(((size_t)(bz * CIN + c)) * HH + xr[v]) * WW + g];
            xs[c * 264 + v * 66 + cc] = val;
        }
    }
    __syncthreads();

    const size_t nbase = (size_t)bz * 16384 + (size_t)ho * 512 + wo0;
    const int wm = (wid & 3) * 16;      // w-GEMM warp M (c), 16 rows
    const int wn = (wid >> 2) * 64;     // w-GEMM warp N (combo)

    for (int s = 0; s < 2; s++) {
        // ---- h compute: thread = (combo = tid&255, jhalf = tid>>8) ----
        {
            int posl = (tid >> 5) & 7;
            int pos  = 8 * s + posl;
            int u = pos >> 2, v = pos & 3;
            int px = lane;
            int j0 = (tid >> 8) * 32;          // 0 or 32
            float R   = rs[v * 66 + 2 * px + u];
            float nrc = -rs[2 * 66 + 2 * px + 2];
            const uint32_t plane = (lane & 1) ? (sb + HSL_B) : (sb + HSH_B);
            const int wordb = ((tid & 255) & ~1) * 2;
            #pragma unroll 8
            for (int jj = 0; jj < 32; jj++) {
                int j = j0 + jj;
                float t = fmaf(R, Ast[j * 16 + pos], fmaf(nrc, W10s[j], b1s[j]));
                t = (t > 0.0f) ? t : 0.2f * t;
                __nv_bfloat16 hb = __float2bfloat16(t);
                float rem = t - __bfloat162float(hb);
                float t_o   = __shfl_xor_sync(0xffffffffu, t, 1);
                float rem_o = __shfl_xor_sync(0xffffffffu, rem, 1);
                uint32_t wH = pk_bf2(t, t_o);
                uint32_t wL = pk_bf2(rem_o, rem);
                uint32_t word = (lane & 1) ? wL : wH;
                sts32(plane + SWC(j * 512 + wordb), word);
            }
        }
        __syncthreads();

        // ---- w-GEMM: warp tile M16 x N64, K=64, 3 combos ----
        {
            float acc[8][4];
            #pragma unroll
            for (int nt = 0; nt < 8; nt++)
                #pragma unroll
                for (int q = 0; q < 4; q++) acc[nt][q] = 0.0f;

            #pragma unroll
            for (int ks = 0; ks < 4; ks++) {
                uint32_t aH[4], aL[4];
                int arow  = wm + (lane & 15);
                int acolb = ks * 32 + ((lane >> 4) << 4);
                uint32_t aoff = SWA(arow * 128 + acolb);
                ldsm4(aH, sb + W2TH_B + aoff);
                ldsm4(aL, sb + W2TL_B + aoff);
                int browb = (ks * 16 + (lane & 15)) * 512;
                #pragma unroll
                for (int g = 0; g < 4; g++) {
                    uint32_t off = SWC(browb + wn * 2 + g * 32 + ((lane >> 4) << 4));
                    uint32_t bh[4], bl[4];
                    ldsm4t(bh, sb + HSH_B + off);
                    ldsm4t(bl, sb + HSL_B + off);
                    mma16816(acc[2*g],   aH, bh);
                    mma16816(acc[2*g+1], aH, bh + 2);
                    mma16816(acc[2*g],   aL, bh);
                    mma16816(acc[2*g+1], aL, bh + 2);
                    mma16816(acc[2*g],   aH, bl);
                    mma16816(acc[2*g+1], aH, bl + 2);
                }
            }

            int r0 = wm + (lane >> 2);
            float b2a = b2s[r0], b2b = b2s[r0 + 8];
            #pragma unroll
            for (int nt = 0; nt < 8; nt++) {
                int col = wn + nt * 8 + (lane & 3) * 2;
                float2 v0, v1;
                v0.x = acc[nt][0] + b2a; v0.y = acc[nt][1] + b2a;
                v1.x = acc[nt][2] + b2b; v1.y = acc[nt][3] + b2b;
                *(float2*)(ws + r0 * 260 + col) = v0;
                *(float2*)(ws + (r0 + 8) * 260 + col) = v1;
            }
        }
        __syncthreads();

        // ---- phase B: warp = (posl = wid&7, chalf = wid>>3), lane = px ----
        {
            int posl = wid & 7;
            int pos  = 8 * s + posl;
            int u = pos >> 2, v = pos & 3;
            int px = lane;
            int c0 = (wid >> 3) * 32;
            const float* xrow = xs + c0 * 264 + v * 66 + 2 * px + u;
            const float* wsr  = ws + c0 * 260 + posl * 32 + px;
            __nv_bfloat16* gmh = g_mh + (size_t)((c0 * 16 + pos)) * NPIX + nbase + px;
            __nv_bfloat16* gml = g_ml + (size_t)((c0 * 16 + pos)) * NPIX + nbase + px;
            #pragma unroll 8
            for (int ci = 0; ci < 32; ci++) {
                float wv = wsr[ci * 260];
                float xv = xrow[ci * 264];
                float mv = wv * xv;
                __nv_bfloat16 hi = __float2bfloat16(mv);
                float rem = mv - __bfloat162float(hi);
                gmh[(size_t)ci * 16 * NPIX] = hi;
                gml[(size_t)ci * 16 * NPIX] = __float2bfloat16(rem);
            }
        }
        __syncthreads();
    }

    if (rcout != nullptr && tid < 32) {
        rcout[nbase + tid] = rs[2 * 66 + 2 * tid + 2];
    }
}

// =====================================================================
// Kernel 2: HMMA bf16 split GEMM, 512 threads (unchanged from R10).
// =====================================================================
#define K2_STAGE 98304
#define K2_SMEM  (2 * K2_STAGE)

__global__ void __launch_bounds__(512, 1)
k2_hmma(const float* __restrict__ bc, float* __restrict__ out)
{
    extern __shared__ char sm2[];
    const uint32_t sb = smem_u32(sm2);
    const int tid  = threadIdx.x;
    const int wid  = tid >> 5;
    const int lane = tid & 31;
    const int n0 = blockIdx.x * 256;
    const int wm = (wid & 3) * 32;
    const int wn = (wid >> 2) * 64;

    float acc[2][8][4];
    #pragma unroll
    for (int mi = 0; mi < 2; mi++)
        #pragma unroll
        for (int nt = 0; nt < 8; nt++)
            #pragma unroll
            for (int q = 0; q < 4; q++) acc[mi][nt][q] = 0.0f;

    auto load_chunk = [&](int c, int s) {
        const uint32_t base = sb + s * K2_STAGE;
        const int k0 = c * 64;
        #pragma unroll
        for (int t = 0; t < 4; t++) {
            int ci = tid + (t & 1) * 512;
            const __nv_bfloat16* W = (t < 2) ? g_WcH : g_WcL;
            int row = ci >> 3, un = ci & 7;
            uint32_t sa = base + ((t < 2) ? 0 : 16384) + SWA(row * 128 + un * 16);
            cp16(sa, W + (size_t)row * KTOT + k0 + un * 8);
        }
        #pragma unroll
        for (int t = 0; t < 8; t++) {
            int ci = tid + (t & 3) * 512;
            const __nv_bfloat16* M = (t < 4) ? g_mh : g_ml;
            int row = ci >> 5, un = ci & 31;
            uint32_t sa = base + ((t < 4) ? 32768 : 65536) + SWC(row * 512 + un * 16);
            cp16(sa, M + (size_t)(k0 + row) * NPIX + n0 + un * 8);
        }
        CP_COMMIT();
    };

    load_chunk(0, 0);
    load_chunk(1, 1);

    for (int c = 0; c < 16; c++) {
        const int s = c & 1;
        if (c == 15) { CP_WAIT0(); } else { CP_WAIT1(); }
        __syncthreads();

        const uint32_t bAh = sb + s * K2_STAGE;
        const uint32_t bAl = bAh + 16384;
        const uint32_t bBh = bAh + 32768;
        const uint32_t bBl = bAh + 65536;

        #pragma unroll
        for (int ks = 0; ks < 4; ks++) {
            uint32_t a_h[2][4], a_l[2][4];
            {
                int arow  = wm + (lane & 15);
                int acolb = ks * 32 + ((lane >> 4) << 4);
                #pragma unroll
                for (int mi = 0; mi < 2; mi++) {
                    uint32_t off = SWA((arow + mi * 16) * 128 + acolb);
                    ldsm4(a_h[mi], bAh + off);
                    ldsm4(a_l[mi], bAl + off);
                }
            }
            int browb = (ks * 16 + (lane & 15)) * 512;
            #pragma unroll
            for (int g = 0; g < 4; g++) {
                uint32_t off = SWC(browb + (wn + g * 16 + ((lane >> 4) << 3)) * 2);
                uint32_t bh[4], bl[4];
                ldsm4t(bh, bBh + off);
                ldsm4t(bl, bBl + off);
                #pragma unroll
                for (int mi = 0; mi < 2; mi++) {
                    mma16816(acc[mi][2*g],   a_h[mi], bh);
                    mma16816(acc[mi][2*g+1], a_h[mi], bh + 2);
                    mma16816(acc[mi][2*g],   a_l[mi], bh);
                    mma16816(acc[mi][2*g+1], a_l[mi], bh + 2);
                    mma16816(acc[mi][2*g],   a_h[mi], bl);
                    mma16816(acc[mi][2*g+1], a_h[mi], bl + 2);
                }
            }
        }
        __syncthreads();
        if (c + 2 < 16) load_chunk(c + 2, s);
    }

    const int bz = n0 >> 14;
    const int ncb = n0 & 16383;
    #pragma unroll
    for (int mi = 0; mi < 2; mi++) {
        int r0 = wm + mi * 16 + (lane >> 2);
        float bv0 = bc[r0], bv1 = bc[r0 + 8];
        float* row0 = out + ((size_t)(bz * COUT + r0))     * 16384 + ncb;
        float* row1 = out + ((size_t)(bz * COUT + r0 + 8)) * 16384 + ncb;
        #pragma unroll
        for (int nt = 0; nt < 8; nt++) {
            int col = wn + nt * 8 + (lane & 3) * 2;
            float2 v0, v1;
            v0.x = acc[mi][nt][0] + bv0; v0.y = acc[mi][nt][1] + bv0;
            v1.x = acc[mi][nt][2] + bv1; v1.y = acc[mi][nt][3] + bv1;
            *(float2*)(row0 + col) = v0;
            *(float2*)(row1 + col) = v1;
        }
    }
}

extern "C" void kernel_launch(void* const* d_in, const int* in_sizes, int n_in,
                              void* d_out, int out_size) {
    const float* x  = (const float*)d_in[0];
    const float* r  = (const float*)d_in[1];
    const float* W1 = (const float*)d_in[2];
    const float* b1 = (const float*)d_in[3];
    const float* W2 = (const float*)d_in[4];
    const float* b2 = (const float*)d_in[5];
    const float* Wc = (const float*)d_in[6];
    const float* bc = (const float*)d_in[7];
    float* out = (float*)d_out;

    cudaFuncSetAttribute(k1_weights, cudaFuncAttributeMaxDynamicSharedMemorySize, SM1_BYTES);
    cudaFuncSetAttribute(k2_hmma, cudaFuncAttributeMaxDynamicSharedMemorySize, K2_SMEM);

    float* rcout = (out_size > OUT0) ? (out + OUT0) : nullptr;

    k0_prep<<<(COUT * KTOT + 255) / 256, 256>>>(Wc, W2, W1);
    dim3 g1(16, 32, 4);
    k1_weights<<<g1, 512, SM1_BYTES>>>(x, r, W1, b1, b2, rcout);
    k2_hmma<<<256, 512, K2_SMEM>>>(bc, out);
}

// round 12
// speedup vs baseline: 1.6116x; 1.0320x over previous
#include <cuda_runtime.h>
#include <cuda_bf16.h>
#include <cstdint>
#include <cstddef>

#define BATCH   4
#define CIN     64
#define COUT    128
#define HH      64
#define WW      1024
#define HO      32
#define WO      512
#define NPIX    65536
#define KTOT    1024
#define OUT0    8388608
#define AZI_C   0.006135923151542565f
#define INC_C   0.0073f

__device__ __nv_bfloat16 g_mh[(size_t)KTOT * NPIX];
__device__ __nv_bfloat16 g_ml[(size_t)KTOT * NPIX];
__device__ __nv_bfloat16 g_WcH[COUT * KTOT];
__device__ __nv_bfloat16 g_WcL[COUT * KTOT];
__device__ __nv_bfloat16 g_W2TH[CIN * CIN];   // [c][j]
__device__ __nv_bfloat16 g_W2TL[CIN * CIN];
__device__ float g_Ast[CIN * 16];             // [j][pos]

__device__ __forceinline__ uint32_t smem_u32(const void* p) {
    uint32_t a;
    asm("{ .reg .u64 t; cvta.to.shared.u64 t, %1; cvt.u32.u64 %0, t; }" : "=r"(a) : "l"(p));
    return a;
}
#define SWA(o) ((o) ^ (((o) >> 3) & 0x70))
#define SWC(o) ((o) ^ (((o) >> 5) & 0x70))

__device__ __forceinline__ void sts32(uint32_t saddr, uint32_t v) {
    asm volatile("st.shared.u32 [%0], %1;" :: "r"(saddr), "r"(v) : "memory");
}
__device__ __forceinline__ uint32_t lds16(uint32_t saddr) {
    uint32_t v;
    asm volatile("{ .reg .u16 t; ld.shared.u16 t, [%1]; cvt.u32.u16 %0, t; }"
        : "=r"(v) : "r"(saddr));
    return v;
}
__device__ __forceinline__ void cp16(uint32_t saddr, const void* gaddr) {
    asm volatile("cp.async.cg.shared.global [%0], [%1], 16;" :: "r"(saddr), "l"(gaddr));
}
#define CP_COMMIT() asm volatile("cp.async.commit_group;" ::: "memory")
#define CP_WAIT1()  asm volatile("cp.async.wait_group 1;" ::: "memory")
#define CP_WAIT0()  asm volatile("cp.async.wait_group 0;" ::: "memory")

__device__ __forceinline__ void ldsm4(uint32_t* r, uint32_t a) {
    asm volatile("ldmatrix.sync.aligned.m8n8.x4.shared.b16 {%0,%1,%2,%3}, [%4];"
        : "=r"(r[0]), "=r"(r[1]), "=r"(r[2]), "=r"(r[3]) : "r"(a));
}
__device__ __forceinline__ void ldsm4t(uint32_t* r, uint32_t a) {
    asm volatile("ldmatrix.sync.aligned.m8n8.x4.trans.shared.b16 {%0,%1,%2,%3}, [%4];"
        : "=r"(r[0]), "=r"(r[1]), "=r"(r[2]), "=r"(r[3]) : "r"(a));
}
__device__ __forceinline__ void mma16816(float* d, const uint32_t* a, const uint32_t* b) {
    asm volatile(
        "mma.sync.aligned.m16n8k16.row.col.f32.bf16.bf16.f32 "
        "{%0,%1,%2,%3}, {%4,%5,%6,%7}, {%8,%9}, {%0,%1,%2,%3};"
        : "+f"(d[0]), "+f"(d[1]), "+f"(d[2]), "+f"(d[3])
        : "r"(a[0]), "r"(a[1]), "r"(a[2]), "r"(a[3]), "r"(b[0]), "r"(b[1]));
}
__device__ __forceinline__ uint32_t pk_bf2(float lo, float hi) {
    uint32_t r;
    asm("cvt.rn.bf16x2.f32 %0, %1, %2;" : "=r"(r) : "f"(hi), "f"(lo));
    return r;
}

// =====================================================================
// Kernel 0: split Wc + W2^T into bf16 hi/lo, precompute Ast
// =====================================================================
__global__ void k0_prep(const float* __restrict__ Wc, const float* __restrict__ W2,
                        const float* __restrict__ W1) {
    int i = blockIdx.x * 256 + threadIdx.x;
    if (i < COUT * KTOT) {
        float v = Wc[i];
        __nv_bfloat16 h = __float2bfloat16(v);
        g_WcH[i] = h;
        g_WcL[i] = __float2bfloat16(v - __bfloat162float(h));
    }
    if (i < CIN * CIN) {
        int j = i >> 6, c = i & 63;
        float v = W2[i];
        __nv_bfloat16 h = __float2bfloat16(v);
        g_W2TH[c * 64 + j] = h;
        g_W2TL[c * 64 + j] = __float2bfloat16(v - __bfloat162float(h));
    }
    if (i < CIN * 16) {
        int j = i >> 4, pos = i & 15;
        int u = pos >> 2, v = pos & 3;
        float du = (float)(u - 2), dv = (float)(v - 2);
        float ca = cosf(AZI_C * dv), sa = sinf(AZI_C * dv);
        float ci = cosf(INC_C * du), si = sinf(INC_C * du);
        g_Ast[i] = ca * ci * W1[j] + ca * si * W1[64 + j] + sa * W1[128 + j];
    }
}

// =====================================================================
// Kernel 1 v4: 16-pixel tile, 256 threads, 2 CTAs/SM.
// hs region (64KB) time-shared: h planes -> w planes.
// x read directly from global in phase B (no xs smem).
// smem byte map (87328 total):
//   0      HSH (32768) | 32768 HSL (32768)   [later: wH / wL planes]
//   65536  W2TH (8192) | 73728 W2TL (8192)
//   81920  Ast (4096)
//   86016  W10 (256) | 86272 b1 (256) | 86528 b2 (256)
//   86784  rs [4][34] (544)
// =====================================================================
#define V4_HSH   0
#define V4_HSL   32768
#define V4_W2TH  65536
#define V4_W2TL  73728
#define V4_AST   81920
#define V4_W10   86016
#define V4_B1    86272
#define V4_B2    86528
#define V4_RS    86784
#define SM1_BYTES 87328

__global__ void __launch_bounds__(256, 2)
k1_weights(const float* __restrict__ x, const float* __restrict__ r,
           const float* __restrict__ W1, const float* __restrict__ b1,
           const float* __restrict__ b2, float* __restrict__ rcout)
{
    extern __shared__ float sm[];
    float* Ast  = sm + V4_AST / 4;
    float* W10s = sm + V4_W10 / 4;
    float* b1s  = sm + V4_B1 / 4;
    float* b2s  = sm + V4_B2 / 4;
    float* rs   = sm + V4_RS / 4;
    char*  smc  = (char*)sm;
    const uint32_t sb = smem_u32(sm);

    const int tid  = threadIdx.x;
    const int lane = tid & 31;
    const int wid  = tid >> 5;          // 0..7
    const int ho   = blockIdx.y;
    const int bz   = blockIdx.z;
    const int wo0  = blockIdx.x * 16;

    // ---- staging ----
    if (tid < 64) { W10s[tid] = W1[tid]; b1s[tid] = b1[tid]; b2s[tid] = b2[tid]; }
    for (int i = tid; i < 1024; i += 256) Ast[i] = g_Ast[i];
    if (tid < 4 * 34) {
        int v = tid / 34, cc = tid % 34;
        int rowp = 2 * ho + v;
        int row  = (rowp == 0) ? (HH - 1) : ((rowp == HH + 1) ? 0 : rowp - 1);
        int colp = 2 * wo0 + cc;
        float val;
        if (colp == 0 || colp == WW + 1) val = 100.0f;
        else val = r[((size_t)bz * HH + row) * WW + (colp - 1)];
        rs[tid] = val;
    }
    for (int i = tid; i < 4096; i += 256) {
        int row = i >> 6, col = i & 63;
        uint32_t off = SWA(row * 128 + col * 2);
        *(__nv_bfloat16*)(smc + V4_W2TH + off) = g_W2TH[i];
        *(__nv_bfloat16*)(smc + V4_W2TL + off) = g_W2TL[i];
    }
    __syncthreads();

    const size_t nbase = (size_t)bz * 16384 + (size_t)ho * 512 + wo0;

    // ---- h compute: thread = combo (pos = tid>>4, px = tid&15) ----
    {
        int pos = tid >> 4;
        int u = pos >> 2, v = pos & 3;
        int px = tid & 15;
        float R   = rs[v * 34 + 2 * px + u];
        float nrc = -rs[2 * 34 + 2 * px + 2];
        const uint32_t plane = (lane & 1) ? (sb + V4_HSL) : (sb + V4_HSH);
        const int wordb = (tid & ~1) * 2;     // pair word byte offset in 512B row
        #pragma unroll 8
        for (int j = 0; j < 64; j++) {
            float t = fmaf(R, Ast[j * 16 + pos], fmaf(nrc, W10s[j], b1s[j]));
            t = (t > 0.0f) ? t : 0.2f * t;
            __nv_bfloat16 hb = __float2bfloat16(t);
            float rem = t - __bfloat162float(hb);
            float t_o   = __shfl_xor_sync(0xffffffffu, t, 1);
            float rem_o = __shfl_xor_sync(0xffffffffu, rem, 1);
            uint32_t wH = pk_bf2(t, t_o);
            uint32_t wL = pk_bf2(rem_o, rem);
            uint32_t word = (lane & 1) ? wL : wH;
            sts32(plane + SWC(j * 512 + wordb), word);
        }
    }
    __syncthreads();

    // ---- w-GEMM: 8 warps, warp tile M16(c) x N128(combo), K=64, 3 combos ----
    {
        const int wm = (wid & 3) * 16;
        const int wn = (wid >> 2) * 128;

        float acc[16][4];
        #pragma unroll
        for (int nt = 0; nt < 16; nt++)
            #pragma unroll
            for (int q = 0; q < 4; q++) acc[nt][q] = 0.0f;

        #pragma unroll
        for (int ks = 0; ks < 4; ks++) {
            uint32_t aH[4], aL[4];
            int arow  = wm + (lane & 15);
            int acolb = ks * 32 + ((lane >> 4) << 4);
            uint32_t aoff = SWA(arow * 128 + acolb);
            ldsm4(aH, sb + V4_W2TH + aoff);
            ldsm4(aL, sb + V4_W2TL + aoff);
            int browb = (ks * 16 + (lane & 15)) * 512;
            #pragma unroll
            for (int g = 0; g < 8; g++) {
                uint32_t off = SWC(browb + wn * 2 + g * 32 + ((lane >> 4) << 4));
                uint32_t bh[4], bl[4];
                ldsm4t(bh, sb + V4_HSH + off);
                ldsm4t(bl, sb + V4_HSL + off);
                mma16816(acc[2*g],   aH, bh);
                mma16816(acc[2*g+1], aH, bh + 2);
                mma16816(acc[2*g],   aL, bh);
                mma16816(acc[2*g+1], aL, bh + 2);
                mma16816(acc[2*g],   aH, bl);
                mma16816(acc[2*g+1], aH, bl + 2);
            }
        }
        __syncthreads();   // hs fully consumed by all warps

        // w = acc + b2, split bf16 hi/lo, write into hs region (reuse)
        int r0 = wm + (lane >> 2);
        int r2 = r0 + 8;
        float b2a = b2s[r0], b2b = b2s[r2];
        #pragma unroll
        for (int nt = 0; nt < 16; nt++) {
            int comb0 = wn + nt * 8 + (lane & 3) * 2;     // even combo
            float w0 = acc[nt][0] + b2a, w1 = acc[nt][1] + b2a;
            float w2 = acc[nt][2] + b2b, w3 = acc[nt][3] + b2b;
            float l0 = w0 - __bfloat162float(__float2bfloat16(w0));
            float l1 = w1 - __bfloat162float(__float2bfloat16(w1));
            float l2 = w2 - __bfloat162float(__float2bfloat16(w2));
            float l3 = w3 - __bfloat162float(__float2bfloat16(w3));
            uint32_t offa = SWC(r0 * 512 + comb0 * 2);
            uint32_t offb = SWC(r2 * 512 + comb0 * 2);
            sts32(sb + V4_HSH + offa, pk_bf2(w0, w1));
            sts32(sb + V4_HSL + offa, pk_bf2(l0, l1));
            sts32(sb + V4_HSH + offb, pk_bf2(w2, w3));
            sts32(sb + V4_HSL + offb, pk_bf2(l2, l3));
        }
    }
    __syncthreads();

    // ---- phase B: m = w * x -> g_m.  warp = 2 pos, lane: px = lane&15 ----
    {
        int pos = 2 * wid + (lane >> 4);     // 0..15
        int u = pos >> 2, v = pos & 3;
        int px = lane & 15;
        int comb = pos * 16 + px;

        int rowp = 2 * ho + v;
        int xrow = (rowp == 0) ? (HH - 1) : ((rowp == HH + 1) ? 0 : rowp - 1);
        int xcol = 2 * (wo0 + px) + u - 1;
        bool valid = (xcol >= 0) && (xcol < WW);
        const float* xbase = x + ((size_t)(bz * CIN) * HH + xrow) * WW + (valid ? xcol : 0);

        const uint32_t wHb = sb + V4_HSH;
        const uint32_t wLb = sb + V4_HSL;
        __nv_bfloat16* gmh = g_mh + (size_t)pos * NPIX + nbase + px;
        __nv_bfloat16* gml = g_ml + (size_t)pos * NPIX + nbase + px;

        #pragma unroll 8
        for (int c = 0; c < 64; c++) {
            uint32_t off = SWC(c * 512 + comb * 2);
            uint32_t whb = lds16(wHb + off);
            uint32_t wlb = lds16(wLb + off);
            float wv = __uint_as_float(whb << 16) + __uint_as_float(wlb << 16);
            float xv = valid ? xbase[(size_t)c * (HH * WW)] : 0.0f;
            float mv = wv * xv;
            __nv_bfloat16 hi = __float2bfloat16(mv);
            float rem = mv - __bfloat162float(hi);
            gmh[(size_t)c * 16 * NPIX] = hi;
            gml[(size_t)c * 16 * NPIX] = __float2bfloat16(rem);
        }
    }

    if (rcout != nullptr && tid < 16) {
        rcout[nbase + tid] = rs[2 * 34 + 2 * tid + 2];
    }
}

// =====================================================================
// Kernel 2: HMMA bf16 split GEMM, 512 threads (unchanged, at pipe floor).
// =====================================================================
#define K2_STAGE 98304
#define K2_SMEM  (2 * K2_STAGE)

__global__ void __launch_bounds__(512, 1)
k2_hmma(const float* __restrict__ bc, float* __restrict__ out)
{
    extern __shared__ char sm2[];
    const uint32_t sb = smem_u32(sm2);
    const int tid  = threadIdx.x;
    const int wid  = tid >> 5;
    const int lane = tid & 31;
    const int n0 = blockIdx.x * 256;
    const int wm = (wid & 3) * 32;
    const int wn = (wid >> 2) * 64;

    float acc[2][8][4];
    #pragma unroll
    for (int mi = 0; mi < 2; mi++)
        #pragma unroll
        for (int nt = 0; nt < 8; nt++)
            #pragma unroll
            for (int q = 0; q < 4; q++) acc[mi][nt][q] = 0.0f;

    auto load_chunk = [&](int c, int s) {
        const uint32_t base = sb + s * K2_STAGE;
        const int k0 = c * 64;
        #pragma unroll
        for (int t = 0; t < 4; t++) {
            int ci = tid + (t & 1) * 512;
            const __nv_bfloat16* W = (t < 2) ? g_WcH : g_WcL;
            int row = ci >> 3, un = ci & 7;
            uint32_t sa = base + ((t < 2) ? 0 : 16384) + SWA(row * 128 + un * 16);
            cp16(sa, W + (size_t)row * KTOT + k0 + un * 8);
        }
        #pragma unroll
        for (int t = 0; t < 8; t++) {
            int ci = tid + (t & 3) * 512;
            const __nv_bfloat16* M = (t < 4) ? g_mh : g_ml;
            int row = ci >> 5, un = ci & 31;
            uint32_t sa = base + ((t < 4) ? 32768 : 65536) + SWC(row * 512 + un * 16);
            cp16(sa, M + (size_t)(k0 + row) * NPIX + n0 + un * 8);
        }
        CP_COMMIT();
    };

    load_chunk(0, 0);
    load_chunk(1, 1);

    for (int c = 0; c < 16; c++) {
        const int s = c & 1;
        if (c == 15) { CP_WAIT0(); } else { CP_WAIT1(); }
        __syncthreads();

        const uint32_t bAh = sb + s * K2_STAGE;
        const uint32_t bAl = bAh + 16384;
        const uint32_t bBh = bAh + 32768;
        const uint32_t bBl = bAh + 65536;

        #pragma unroll
        for (int ks = 0; ks < 4; ks++) {
            uint32_t a_h[2][4], a_l[2][4];
            {
                int arow  = wm + (lane & 15);
                int acolb = ks * 32 + ((lane >> 4) << 4);
                #pragma unroll
                for (int mi = 0; mi < 2; mi++) {
                    uint32_t off = SWA((arow + mi * 16) * 128 + acolb);
                    ldsm4(a_h[mi], bAh + off);
                    ldsm4(a_l[mi], bAl + off);
                }
            }
            int browb = (ks * 16 + (lane & 15)) * 512;
            #pragma unroll
            for (int g = 0; g < 4; g++) {
                uint32_t off = SWC(browb + (wn + g * 16 + ((lane >> 4) << 3)) * 2);
                uint32_t bh[4], bl[4];
                ldsm4t(bh, bBh + off);
                ldsm4t(bl, bBl + off);
                #pragma unroll
                for (int mi = 0; mi < 2; mi++) {
                    mma16816(acc[mi][2*g],   a_h[mi], bh);
                    mma16816(acc[mi][2*g+1], a_h[mi], bh + 2);
                    mma16816(acc[mi][2*g],   a_l[mi], bh);
                    mma16816(acc[mi][2*g+1], a_l[mi], bh + 2);
                    mma16816(acc[mi][2*g],   a_h[mi], bl);
                    mma16816(acc[mi][2*g+1], a_h[mi], bl + 2);
                }
            }
        }
        __syncthreads();
        if (c + 2 < 16) load_chunk(c + 2, s);
    }

    const int bz = n0 >> 14;
    const int ncb = n0 & 16383;
    #pragma unroll
    for (int mi = 0; mi < 2; mi++) {
        int r0 = wm + mi * 16 + (lane >> 2);
        float bv0 = bc[r0], bv1 = bc[r0 + 8];
        float* row0 = out + ((size_t)(bz * COUT + r0))     * 16384 + ncb;
        float* row1 = out + ((size_t)(bz * COUT + r0 + 8)) * 16384 + ncb;
        #pragma unroll
        for (int nt = 0; nt < 8; nt++) {
            int col = wn + nt * 8 + (lane & 3) * 2;
            float2 v0, v1;
            v0.x = acc[mi][nt][0] + bv0; v0.y = acc[mi][nt][1] + bv0;
            v1.x = acc[mi][nt][2] + bv1; v1.y = acc[mi][nt][3] + bv1;
            *(float2*)(row0 + col) = v0;
            *(float2*)(row1 + col) = v1;
        }
    }
}

extern "C" void kernel_launch(void* const* d_in, const int* in_sizes, int n_in,
                              void* d_out, int out_size) {
    const float* x  = (const float*)d_in[0];
    const float* r  = (const float*)d_in[1];
    const float* W1 = (const float*)d_in[2];
    const float* b1 = (const float*)d_in[3];
    const float* W2 = (const float*)d_in[4];
    const float* b2 = (const float*)d_in[5];
    const float* Wc = (const float*)d_in[6];
    const float* bc = (const float*)d_in[7];
    float* out = (float*)d_out;

    cudaFuncSetAttribute(k1_weights, cudaFuncAttributeMaxDynamicSharedMemorySize, SM1_BYTES);
    cudaFuncSetAttribute(k2_hmma, cudaFuncAttributeMaxDynamicSharedMemorySize, K2_SMEM);

    float* rcout = (out_size > OUT0) ? (out + OUT0) : nullptr;

    k0_prep<<<(COUT * KTOT + 255) / 256, 256>>>(Wc, W2, W1);
    dim3 g1(32, 32, 4);
    k1_weights<<<g1, 256, SM1_BYTES>>>(x, r, W1, b1, b2, rcout);
    k2_hmma<<<256, 512, K2_SMEM>>>(bc, out);
}

// round 13
// speedup vs baseline: 2.0227x; 1.2551x over previous
#include <cuda_runtime.h>
#include <cuda_fp16.h>
#include <cstdint>
#include <cstddef>

#define BATCH   4
#define CIN     64
#define COUT    128
#define HH      64
#define WW      1024
#define HO      32
#define WO      512
#define NPIX    65536
#define KTOT    1024
#define OUT0    8388608
#define AZI_C   0.006135923151542565f
#define INC_C   0.0073f

__device__ __half g_m[(size_t)KTOT * NPIX];     // single fp16 plane
__device__ __half g_WcH[COUT * KTOT];
__device__ __half g_WcL[COUT * KTOT];
__device__ __half g_W2TH[CIN * CIN];            // [c][j]
__device__ __half g_W2TL[CIN * CIN];
__device__ float  g_Ast[CIN * 16];              // [j][pos]

__device__ __forceinline__ uint32_t smem_u32(const void* p) {
    uint32_t a;
    asm("{ .reg .u64 t; cvta.to.shared.u64 t, %1; cvt.u32.u64 %0, t; }" : "=r"(a) : "l"(p));
    return a;
}
#define SWA(o) ((o) ^ (((o) >> 3) & 0x70))
#define SWC(o) ((o) ^ (((o) >> 5) & 0x70))

__device__ __forceinline__ void sts32(uint32_t saddr, uint32_t v) {
    asm volatile("st.shared.u32 [%0], %1;" :: "r"(saddr), "r"(v) : "memory");
}
__device__ __forceinline__ void cp16(uint32_t saddr, const void* gaddr) {
    asm volatile("cp.async.cg.shared.global [%0], [%1], 16;" :: "r"(saddr), "l"(gaddr));
}
#define CP_COMMIT() asm volatile("cp.async.commit_group;" ::: "memory")
#define CP_WAIT1()  asm volatile("cp.async.wait_group 1;" ::: "memory")
#define CP_WAIT0()  asm volatile("cp.async.wait_group 0;" ::: "memory")

__device__ __forceinline__ void ldsm4(uint32_t* r, uint32_t a) {
    asm volatile("ldmatrix.sync.aligned.m8n8.x4.shared.b16 {%0,%1,%2,%3}, [%4];"
        : "=r"(r[0]), "=r"(r[1]), "=r"(r[2]), "=r"(r[3]) : "r"(a));
}
__device__ __forceinline__ void ldsm4t(uint32_t* r, uint32_t a) {
    asm volatile("ldmatrix.sync.aligned.m8n8.x4.trans.shared.b16 {%0,%1,%2,%3}, [%4];"
        : "=r"(r[0]), "=r"(r[1]), "=r"(r[2]), "=r"(r[3]) : "r"(a));
}
__device__ __forceinline__ void mma16816(float* d, const uint32_t* a, const uint32_t* b) {
    asm volatile(
        "mma.sync.aligned.m16n8k16.row.col.f32.f16.f16.f32 "
        "{%0,%1,%2,%3}, {%4,%5,%6,%7}, {%8,%9}, {%0,%1,%2,%3};"
        : "+f"(d[0]), "+f"(d[1]), "+f"(d[2]), "+f"(d[3])
        : "r"(a[0]), "r"(a[1]), "r"(a[2]), "r"(a[3]), "r"(b[0]), "r"(b[1]));
}
// pack fp16x2: lo -> lower 16 bits, hi -> upper 16 bits
__device__ __forceinline__ uint32_t pk_h2(float lo, float hi) {
    uint32_t r;
    asm("cvt.rn.f16x2.f32 %0, %1, %2;" : "=r"(r) : "f"(hi), "f"(lo));
    return r;
}

// =====================================================================
// Kernel 0: fp16 hi/lo splits of Wc and W2^T; precompute Ast
// =====================================================================
__global__ void k0_prep(const float* __restrict__ Wc, const float* __restrict__ W2,
                        const float* __restrict__ W1) {
    int i = blockIdx.x * 256 + threadIdx.x;
    if (i < COUT * KTOT) {
        float v = Wc[i];
        __half h = __float2half_rn(v);
        g_WcH[i] = h;
        g_WcL[i] = __float2half_rn(v - __half2float(h));
    }
    if (i < CIN * CIN) {
        int j = i >> 6, c = i & 63;
        float v = W2[i];
        __half h = __float2half_rn(v);
        g_W2TH[c * 64 + j] = h;
        g_W2TL[c * 64 + j] = __float2half_rn(v - __half2float(h));
    }
    if (i < CIN * 16) {
        int j = i >> 4, pos = i & 15;
        int u = pos >> 2, v = pos & 3;
        float du = (float)(u - 2), dv = (float)(v - 2);
        float ca = cosf(AZI_C * dv), sa = sinf(AZI_C * dv);
        float ci = cosf(INC_C * du), si = sinf(INC_C * du);
        g_Ast[i] = ca * ci * W1[j] + ca * si * W1[64 + j] + sa * W1[128 + j];
    }
}

// =====================================================================
// Kernel 1 v5: fp16 path. 16-px tile, 256 threads, 2 CTAs/SM.
// Region 0..64K time-shared: h fp16 plane (32K) -> w f32 [64][256] (64K).
// w-GEMM: w = (W2h + W2l) * h_fp16  (2 combos).
// smem map: 0 HS/WS (65536) | 65536 W2TH 8K | 73728 W2TL 8K |
//           81920 Ast 4K | 86016 W10 | 86272 b1 | 86528 b2 | 86784 rs(544)
// =====================================================================
#define V5_HS    0
#define V5_W2TH  65536
#define V5_W2TL  73728
#define V5_AST   81920
#define V5_W10   86016
#define V5_B1    86272
#define V5_B2    86528
#define V5_RS    86784
#define SM1_BYTES 87328

__global__ void __launch_bounds__(256, 2)
k1_weights(const float* __restrict__ x, const float* __restrict__ r,
           const float* __restrict__ W1, const float* __restrict__ b1,
           const float* __restrict__ b2, float* __restrict__ rcout)
{
    extern __shared__ float sm[];
    float* Ast  = sm + V5_AST / 4;
    float* W10s = sm + V5_W10 / 4;
    float* b1s  = sm + V5_B1 / 4;
    float* b2s  = sm + V5_B2 / 4;
    float* rs   = sm + V5_RS / 4;
    float* wsf  = sm + V5_HS / 4;       // w f32 [64][256] (after h consumed)
    char*  smc  = (char*)sm;
    const uint32_t sb = smem_u32(sm);

    const int tid  = threadIdx.x;
    const int lane = tid & 31;
    const int wid  = tid >> 5;          // 0..7
    const int ho   = blockIdx.y;
    const int bz   = blockIdx.z;
    const int wo0  = blockIdx.x * 16;

    if (tid < 64) { W10s[tid] = W1[tid]; b1s[tid] = b1[tid]; b2s[tid] = b2[tid]; }
    for (int i = tid; i < 1024; i += 256) Ast[i] = g_Ast[i];
    if (tid < 4 * 34) {
        int v = tid / 34, cc = tid % 34;
        int rowp = 2 * ho + v;
        int row  = (rowp == 0) ? (HH - 1) : ((rowp == HH + 1) ? 0 : rowp - 1);
        int colp = 2 * wo0 + cc;
        float val;
        if (colp == 0 || colp == WW + 1) val = 100.0f;
        else val = r[((size_t)bz * HH + row) * WW + (colp - 1)];
        rs[tid] = val;
    }
    for (int i = tid; i < 4096; i += 256) {
        int row = i >> 6, col = i & 63;
        uint32_t off = SWA(row * 128 + col * 2);
        *(__half*)(smc + V5_W2TH + off) = g_W2TH[i];
        *(__half*)(smc + V5_W2TL + off) = g_W2TL[i];
    }
    __syncthreads();

    const size_t nbase = (size_t)bz * 16384 + (size_t)ho * 512 + wo0;

    // ---- h compute: thread = combo (pos = tid>>4, px = tid&15), fp16 plane ----
    {
        int pos = tid >> 4;
        int u = pos >> 2, v = pos & 3;
        int px = tid & 15;
        float R   = rs[v * 34 + 2 * px + u];
        float nrc = -rs[2 * 34 + 2 * px + 2];
        const int wordb = (tid & ~1) * 2;
        const bool evenl = ((lane & 1) == 0);
        #pragma unroll 8
        for (int j = 0; j < 64; j++) {
            float t = fmaf(R, Ast[j * 16 + pos], fmaf(nrc, W10s[j], b1s[j]));
            t = (t > 0.0f) ? t : 0.2f * t;
            float t_o = __shfl_xor_sync(0xffffffffu, t, 1);
            if (evenl) {
                uint32_t word = pk_h2(t, t_o);     // lo = even combo, hi = odd combo
                sts32(sb + V5_HS + SWC(j * 512 + wordb), word);
            }
        }
    }
    __syncthreads();

    // ---- w-GEMM: 8 warps, warp tile M16(c) x N128(combo), K=64, 2 combos ----
    {
        const int wm = (wid & 3) * 16;
        const int wn = (wid >> 2) * 128;

        float acc[16][4];
        #pragma unroll
        for (int nt = 0; nt < 16; nt++)
            #pragma unroll
            for (int q = 0; q < 4; q++) acc[nt][q] = 0.0f;

        #pragma unroll
        for (int ks = 0; ks < 4; ks++) {
            uint32_t aH[4], aL[4];
            int arow  = wm + (lane & 15);
            int acolb = ks * 32 + ((lane >> 4) << 4);
            uint32_t aoff = SWA(arow * 128 + acolb);
            ldsm4(aH, sb + V5_W2TH + aoff);
            ldsm4(aL, sb + V5_W2TL + aoff);
            int browb = (ks * 16 + (lane & 15)) * 512;
            #pragma unroll
            for (int g = 0; g < 8; g++) {
                uint32_t off = SWC(browb + wn * 2 + g * 32 + ((lane >> 4) << 4));
                uint32_t bh[4];
                ldsm4t(bh, sb + V5_HS + off);
                mma16816(acc[2*g],   aH, bh);
                mma16816(acc[2*g+1], aH, bh + 2);
                mma16816(acc[2*g],   aL, bh);
                mma16816(acc[2*g+1], aL, bh + 2);
            }
        }
        __syncthreads();   // h fully consumed by all warps

        // w = acc + b2 -> f32 into region (reuse)
        int r0 = wm + (lane >> 2);
        int r2 = r0 + 8;
        float b2a = b2s[r0], b2b = b2s[r2];
        #pragma unroll
        for (int nt = 0; nt < 16; nt++) {
            int col = wn + nt * 8 + (lane & 3) * 2;
            float2 v0, v1;
            v0.x = acc[nt][0] + b2a; v0.y = acc[nt][1] + b2a;
            v1.x = acc[nt][2] + b2b; v1.y = acc[nt][3] + b2b;
            *(float2*)(wsf + r0 * 256 + col) = v0;
            *(float2*)(wsf + r2 * 256 + col) = v1;
        }
    }
    __syncthreads();

    // ---- phase B: m = w * x -> g_m (single fp16 plane) ----
    {
        int pos = 2 * wid + (lane >> 4);     // 0..15
        int u = pos >> 2, v = pos & 3;
        int px = lane & 15;
        int comb = pos * 16 + px;

        int rowp = 2 * ho + v;
        int xrow = (rowp == 0) ? (HH - 1) : ((rowp == HH + 1) ? 0 : rowp - 1);
        int xcol = 2 * (wo0 + px) + u - 1;
        bool valid = (xcol >= 0) && (xcol < WW);
        const float* xbase = x + ((size_t)(bz * CIN) * HH + xrow) * WW + (valid ? xcol : 0);

        __half* gm = g_m + (size_t)pos * NPIX + nbase + px;
        #pragma unroll 8
        for (int c = 0; c < 64; c++) {
            float wv = wsf[c * 256 + comb];
            float xv = valid ? xbase[(size_t)c * (HH * WW)] : 0.0f;
            gm[(size_t)c * 16 * NPIX] = __float2half_rn(wv * xv);
        }
    }

    if (rcout != nullptr && tid < 16) {
        rcout[nbase + tid] = rs[2 * 34 + 2 * tid + 2];
    }
}

// =====================================================================
// Kernel 2 v3: fp16 2-combo GEMM. out = (WcH + WcL) * m_fp16.
// 512 threads, N-tile 256, stage 64KB x2.
// Stage: Ah 16K | Al 16K | B 32K. A rows 128B SWA; B rows 512B SWC.
// =====================================================================
#define K2_STAGE 65536
#define K2_SMEM  (2 * K2_STAGE)

__global__ void __launch_bounds__(512, 1)
k2_hmma(const float* __restrict__ bc, float* __restrict__ out)
{
    extern __shared__ char sm2[];
    const uint32_t sb = smem_u32(sm2);
    const int tid  = threadIdx.x;
    const int wid  = tid >> 5;
    const int lane = tid & 31;
    const int n0 = blockIdx.x * 256;
    const int wm = (wid & 3) * 32;
    const int wn = (wid >> 2) * 64;

    float acc[2][8][4];
    #pragma unroll
    for (int mi = 0; mi < 2; mi++)
        #pragma unroll
        for (int nt = 0; nt < 8; nt++)
            #pragma unroll
            for (int q = 0; q < 4; q++) acc[mi][nt][q] = 0.0f;

    auto load_chunk = [&](int c, int s) {
        const uint32_t base = sb + s * K2_STAGE;
        const int k0 = c * 64;
        #pragma unroll
        for (int t = 0; t < 4; t++) {     // A planes: 2 x 1024 units
            int ci = tid + (t & 1) * 512;
            const __half* W = (t < 2) ? g_WcH : g_WcL;
            int row = ci >> 3, un = ci & 7;
            uint32_t sa = base + ((t < 2) ? 0 : 16384) + SWA(row * 128 + un * 16);
            cp16(sa, W + (size_t)row * KTOT + k0 + un * 8);
        }
        #pragma unroll
        for (int t = 0; t < 4; t++) {     // B: 2048 units
            int ci = tid + t * 512;
            int row = ci >> 5, un = ci & 31;
            uint32_t sa = base + 32768 + SWC(row * 512 + un * 16);
            cp16(sa, g_m + (size_t)(k0 + row) * NPIX + n0 + un * 8);
        }
        CP_COMMIT();
    };

    load_chunk(0, 0);
    load_chunk(1, 1);

    for (int c = 0; c < 16; c++) {
        const int s = c & 1;
        if (c == 15) { CP_WAIT0(); } else { CP_WAIT1(); }
        __syncthreads();

        const uint32_t bAh = sb + s * K2_STAGE;
        const uint32_t bAl = bAh + 16384;
        const uint32_t bB  = bAh + 32768;

        #pragma unroll
        for (int ks = 0; ks < 4; ks++) {
            uint32_t a_h[2][4], a_l[2][4];
            {
                int arow  = wm + (lane & 15);
                int acolb = ks * 32 + ((lane >> 4) << 4);
                #pragma unroll
                for (int mi = 0; mi < 2; mi++) {
                    uint32_t off = SWA((arow + mi * 16) * 128 + acolb);
                    ldsm4(a_h[mi], bAh + off);
                    ldsm4(a_l[mi], bAl + off);
                }
            }
            int browb = (ks * 16 + (lane & 15)) * 512;
            #pragma unroll
            for (int g = 0; g < 4; g++) {
                uint32_t off = SWC(browb + (wn + g * 16 + ((lane >> 4) << 3)) * 2);
                uint32_t bh[4];
                ldsm4t(bh, bB + off);
                #pragma unroll
                for (int mi = 0; mi < 2; mi++) {
                    mma16816(acc[mi][2*g],   a_h[mi], bh);
                    mma16816(acc[mi][2*g+1], a_h[mi], bh + 2);
                    mma16816(acc[mi][2*g],   a_l[mi], bh);
                    mma16816(acc[mi][2*g+1], a_l[mi], bh + 2);
                }
            }
        }
        __syncthreads();
        if (c + 2 < 16) load_chunk(c + 2, s);
    }

    const int bz = n0 >> 14;
    const int ncb = n0 & 16383;
    #pragma unroll
    for (int mi = 0; mi < 2; mi++) {
        int r0 = wm + mi * 16 + (lane >> 2);
        float bv0 = bc[r0], bv1 = bc[r0 + 8];
        float* row0 = out + ((size_t)(bz * COUT + r0))     * 16384 + ncb;
        float* row1 = out + ((size_t)(bz * COUT + r0 + 8)) * 16384 + ncb;
        #pragma unroll
        for (int nt = 0; nt < 8; nt++) {
            int col = wn + nt * 8 + (lane & 3) * 2;
            float2 v0, v1;
            v0.x = acc[mi][nt][0] + bv0; v0.y = acc[mi][nt][1] + bv0;
            v1.x = acc[mi][nt][2] + bv1; v1.y = acc[mi][nt][3] + bv1;
            *(float2*)(row0 + col) = v0;
            *(float2*)(row1 + col) = v1;
        }
    }
}

extern "C" void kernel_launch(void* const* d_in, const int* in_sizes, int n_in,
                              void* d_out, int out_size) {
    const float* x  = (const float*)d_in[0];
    const float* r  = (const float*)d_in[1];
    const float* W1 = (const float*)d_in[2];
    const float* b1 = (const float*)d_in[3];
    const float* W2 = (const float*)d_in[4];
    const float* b2 = (const float*)d_in[5];
    const float* Wc = (const float*)d_in[6];
    const float* bc = (const float*)d_in[7];
    float* out = (float*)d_out;

    cudaFuncSetAttribute(k1_weights, cudaFuncAttributeMaxDynamicSharedMemorySize, SM1_BYTES);
    cudaFuncSetAttribute(k2_hmma, cudaFuncAttributeMaxDynamicSharedMemorySize, K2_SMEM);

    float* rcout = (out_size > OUT0) ? (out + OUT0) : nullptr;

    k0_prep<<<(COUT * KTOT + 255) / 256, 256>>>(Wc, W2, W1);
    dim3 g1(32, 32, 4);
    k1_weights<<<g1, 256, SM1_BYTES>>>(x, r, W1, b1, b2, rcout);
    k2_hmma<<<256, 512, K2_SMEM>>>(bc, out);
}

// round 14
// speedup vs baseline: 2.2610x; 1.1178x over previous
#include <cuda_runtime.h>
#include <cuda_fp16.h>
#include <cstdint>
#include <cstddef>

#define BATCH   4
#define CIN     64
#define COUT    128
#define HH      64
#define WW      1024
#define HO      32
#define WO      512
#define NPIX    65536
#define KTOT    1024
#define OUT0    8388608
#define AZI_C   0.006135923151542565f
#define INC_C   0.0073f

__device__ __half g_m[(size_t)KTOT * NPIX];     // single fp16 plane
__device__ __half g_WcH[COUT * KTOT];           // fp16(Wc), single plane
__device__ __half g_W2TH[CIN * CIN];            // [c][j]
__device__ __half g_W2TL[CIN * CIN];
__device__ float  g_Ast[CIN * 16];              // [j][pos]

__device__ __forceinline__ uint32_t smem_u32(const void* p) {
    uint32_t a;
    asm("{ .reg .u64 t; cvta.to.shared.u64 t, %1; cvt.u32.u64 %0, t; }" : "=r"(a) : "l"(p));
    return a;
}
#define SWA(o) ((o) ^ (((o) >> 3) & 0x70))
#define SWC(o) ((o) ^ (((o) >> 5) & 0x70))

__device__ __forceinline__ void sts32(uint32_t saddr, uint32_t v) {
    asm volatile("st.shared.u32 [%0], %1;" :: "r"(saddr), "r"(v) : "memory");
}
__device__ __forceinline__ void cp16(uint32_t saddr, const void* gaddr) {
    asm volatile("cp.async.cg.shared.global [%0], [%1], 16;" :: "r"(saddr), "l"(gaddr));
}
#define CP_COMMIT() asm volatile("cp.async.commit_group;" ::: "memory")
#define CP_WAIT1()  asm volatile("cp.async.wait_group 1;" ::: "memory")
#define CP_WAIT0()  asm volatile("cp.async.wait_group 0;" ::: "memory")

__device__ __forceinline__ void ldsm4(uint32_t* r, uint32_t a) {
    asm volatile("ldmatrix.sync.aligned.m8n8.x4.shared.b16 {%0,%1,%2,%3}, [%4];"
        : "=r"(r[0]), "=r"(r[1]), "=r"(r[2]), "=r"(r[3]) : "r"(a));
}
__device__ __forceinline__ void ldsm4t(uint32_t* r, uint32_t a) {
    asm volatile("ldmatrix.sync.aligned.m8n8.x4.trans.shared.b16 {%0,%1,%2,%3}, [%4];"
        : "=r"(r[0]), "=r"(r[1]), "=r"(r[2]), "=r"(r[3]) : "r"(a));
}
__device__ __forceinline__ void mma16816(float* d, const uint32_t* a, const uint32_t* b) {
    asm volatile(
        "mma.sync.aligned.m16n8k16.row.col.f32.f16.f16.f32 "
        "{%0,%1,%2,%3}, {%4,%5,%6,%7}, {%8,%9}, {%0,%1,%2,%3};"
        : "+f"(d[0]), "+f"(d[1]), "+f"(d[2]), "+f"(d[3])
        : "r"(a[0]), "r"(a[1]), "r"(a[2]), "r"(a[3]), "r"(b[0]), "r"(b[1]));
}
__device__ __forceinline__ uint32_t pk_h2(float lo, float hi) {
    uint32_t r;
    asm("cvt.rn.f16x2.f32 %0, %1, %2;" : "=r"(r) : "f"(hi), "f"(lo));
    return r;
}

// =====================================================================
// Kernel 0: fp16(Wc); fp16 hi/lo split of W2^T; Ast
// =====================================================================
__global__ void k0_prep(const float* __restrict__ Wc, const float* __restrict__ W2,
                        const float* __restrict__ W1) {
    int i = blockIdx.x * 256 + threadIdx.x;
    if (i < COUT * KTOT) {
        g_WcH[i] = __float2half_rn(Wc[i]);
    }
    if (i < CIN * CIN) {
        int j = i >> 6, c = i & 63;
        float v = W2[i];
        __half h = __float2half_rn(v);
        g_W2TH[c * 64 + j] = h;
        g_W2TL[c * 64 + j] = __float2half_rn(v - __half2float(h));
    }
    if (i < CIN * 16) {
        int j = i >> 4, pos = i & 15;
        int u = pos >> 2, v = pos & 3;
        float du = (float)(u - 2), dv = (float)(v - 2);
        float ca = cosf(AZI_C * dv), sa = sinf(AZI_C * dv);
        float ci = cosf(INC_C * du), si = sinf(INC_C * du);
        g_Ast[i] = ca * ci * W1[j] + ca * si * W1[64 + j] + sa * W1[128 + j];
    }
}

// =====================================================================
// Kernel 1 (unchanged from R13): fp16 path, 16-px tile, 2 CTAs/SM.
// =====================================================================
#define V5_HS    0
#define V5_W2TH  65536
#define V5_W2TL  73728
#define V5_AST   81920
#define V5_W10   86016
#define V5_B1    86272
#define V5_B2    86528
#define V5_RS    86784
#define SM1_BYTES 87328

__global__ void __launch_bounds__(256, 2)
k1_weights(const float* __restrict__ x, const float* __restrict__ r,
           const float* __restrict__ W1, const float* __restrict__ b1,
           const float* __restrict__ b2, float* __restrict__ rcout)
{
    extern __shared__ float sm[];
    float* Ast  = sm + V5_AST / 4;
    float* W10s = sm + V5_W10 / 4;
    float* b1s  = sm + V5_B1 / 4;
    float* b2s  = sm + V5_B2 / 4;
    float* rs   = sm + V5_RS / 4;
    float* wsf  = sm + V5_HS / 4;
    char*  smc  = (char*)sm;
    const uint32_t sb = smem_u32(sm);

    const int tid  = threadIdx.x;
    const int lane = tid & 31;
    const int wid  = tid >> 5;
    const int ho   = blockIdx.y;
    const int bz   = blockIdx.z;
    const int wo0  = blockIdx.x * 16;

    if (tid < 64) { W10s[tid] = W1[tid]; b1s[tid] = b1[tid]; b2s[tid] = b2[tid]; }
    for (int i = tid; i < 1024; i += 256) Ast[i] = g_Ast[i];
    if (tid < 4 * 34) {
        int v = tid / 34, cc = tid % 34;
        int rowp = 2 * ho + v;
        int row  = (rowp == 0) ? (HH - 1) : ((rowp == HH + 1) ? 0 : rowp - 1);
        int colp = 2 * wo0 + cc;
        float val;
        if (colp == 0 || colp == WW + 1) val = 100.0f;
        else val = r[((size_t)bz * HH + row) * WW + (colp - 1)];
        rs[tid] = val;
    }
    for (int i = tid; i < 4096; i += 256) {
        int row = i >> 6, col = i & 63;
        uint32_t off = SWA(row * 128 + col * 2);
        *(__half*)(smc + V5_W2TH + off) = g_W2TH[i];
        *(__half*)(smc + V5_W2TL + off) = g_W2TL[i];
    }
    __syncthreads();

    const size_t nbase = (size_t)bz * 16384 + (size_t)ho * 512 + wo0;

    // ---- h compute -> fp16 plane ----
    {
        int pos = tid >> 4;
        int u = pos >> 2, v = pos & 3;
        int px = tid & 15;
        float R   = rs[v * 34 + 2 * px + u];
        float nrc = -rs[2 * 34 + 2 * px + 2];
        const int wordb = (tid & ~1) * 2;
        const bool evenl = ((lane & 1) == 0);
        #pragma unroll 8
        for (int j = 0; j < 64; j++) {
            float t = fmaf(R, Ast[j * 16 + pos], fmaf(nrc, W10s[j], b1s[j]));
            t = (t > 0.0f) ? t : 0.2f * t;
            float t_o = __shfl_xor_sync(0xffffffffu, t, 1);
            if (evenl) {
                uint32_t word = pk_h2(t, t_o);
                sts32(sb + V5_HS + SWC(j * 512 + wordb), word);
            }
        }
    }
    __syncthreads();

    // ---- w-GEMM: 8 warps, M16(c) x N128(combo), K=64, 2 combos ----
    {
        const int wm = (wid & 3) * 16;
        const int wn = (wid >> 2) * 128;

        float acc[16][4];
        #pragma unroll
        for (int nt = 0; nt < 16; nt++)
            #pragma unroll
            for (int q = 0; q < 4; q++) acc[nt][q] = 0.0f;

        #pragma unroll
        for (int ks = 0; ks < 4; ks++) {
            uint32_t aH[4], aL[4];
            int arow  = wm + (lane & 15);
            int acolb = ks * 32 + ((lane >> 4) << 4);
            uint32_t aoff = SWA(arow * 128 + acolb);
            ldsm4(aH, sb + V5_W2TH + aoff);
            ldsm4(aL, sb + V5_W2TL + aoff);
            int browb = (ks * 16 + (lane & 15)) * 512;
            #pragma unroll
            for (int g = 0; g < 8; g++) {
                uint32_t off = SWC(browb + wn * 2 + g * 32 + ((lane >> 4) << 4));
                uint32_t bh[4];
                ldsm4t(bh, sb + V5_HS + off);
                mma16816(acc[2*g],   aH, bh);
                mma16816(acc[2*g+1], aH, bh + 2);
                mma16816(acc[2*g],   aL, bh);
                mma16816(acc[2*g+1], aL, bh + 2);
            }
        }
        __syncthreads();

        int r0 = wm + (lane >> 2);
        int r2 = r0 + 8;
        float b2a = b2s[r0], b2b = b2s[r2];
        #pragma unroll
        for (int nt = 0; nt < 16; nt++) {
            int col = wn + nt * 8 + (lane & 3) * 2;
            float2 v0, v1;
            v0.x = acc[nt][0] + b2a; v0.y = acc[nt][1] + b2a;
            v1.x = acc[nt][2] + b2b; v1.y = acc[nt][3] + b2b;
            *(float2*)(wsf + r0 * 256 + col) = v0;
            *(float2*)(wsf + r2 * 256 + col) = v1;
        }
    }
    __syncthreads();

    // ---- phase B: m = w * x -> g_m (fp16) ----
    {
        int pos = 2 * wid + (lane >> 4);
        int u = pos >> 2, v = pos & 3;
        int px = lane & 15;
        int comb = pos * 16 + px;

        int rowp = 2 * ho + v;
        int xrow = (rowp == 0) ? (HH - 1) : ((rowp == HH + 1) ? 0 : rowp - 1);
        int xcol = 2 * (wo0 + px) + u - 1;
        bool valid = (xcol >= 0) && (xcol < WW);
        const float* xbase = x + ((size_t)(bz * CIN) * HH + xrow) * WW + (valid ? xcol : 0);

        __half* gm = g_m + (size_t)pos * NPIX + nbase + px;
        #pragma unroll 8
        for (int c = 0; c < 64; c++) {
            float wv = wsf[c * 256 + comb];
            float xv = valid ? xbase[(size_t)c * (HH * WW)] : 0.0f;
            gm[(size_t)c * 16 * NPIX] = __float2half_rn(wv * xv);
        }
    }

    if (rcout != nullptr && tid < 16) {
        rcout[nbase + tid] = rs[2 * 34 + 2 * tid + 2];
    }
}

// =====================================================================
// Kernel 2 v4: fp16 1-combo GEMM. out = fp16(Wc) * m_fp16 + bc.
// 512 threads, N-tile 256, stage 48KB x2: A 16K | B 32K.
// =====================================================================
#define K2_STAGE 49152
#define K2_SMEM  (2 * K2_STAGE)

__global__ void __launch_bounds__(512, 1)
k2_hmma(const float* __restrict__ bc, float* __restrict__ out)
{
    extern __shared__ char sm2[];
    const uint32_t sb = smem_u32(sm2);
    const int tid  = threadIdx.x;
    const int wid  = tid >> 5;
    const int lane = tid & 31;
    const int n0 = blockIdx.x * 256;
    const int wm = (wid & 3) * 32;
    const int wn = (wid >> 2) * 64;

    float acc[2][8][4];
    #pragma unroll
    for (int mi = 0; mi < 2; mi++)
        #pragma unroll
        for (int nt = 0; nt < 8; nt++)
            #pragma unroll
            for (int q = 0; q < 4; q++) acc[mi][nt][q] = 0.0f;

    auto load_chunk = [&](int c, int s) {
        const uint32_t base = sb + s * K2_STAGE;
        const int k0 = c * 64;
        #pragma unroll
        for (int t = 0; t < 2; t++) {     // A: 1024 units
            int ci = tid + t * 512;
            int row = ci >> 3, un = ci & 7;
            uint32_t sa = base + SWA(row * 128 + un * 16);
            cp16(sa, g_WcH + (size_t)row * KTOT + k0 + un * 8);
        }
        #pragma unroll
        for (int t = 0; t < 4; t++) {     // B: 2048 units
            int ci = tid + t * 512;
            int row = ci >> 5, un = ci & 31;
            uint32_t sa = base + 16384 + SWC(row * 512 + un * 16);
            cp16(sa, g_m + (size_t)(k0 + row) * NPIX + n0 + un * 8);
        }
        CP_COMMIT();
    };

    load_chunk(0, 0);
    load_chunk(1, 1);

    for (int c = 0; c < 16; c++) {
        const int s = c & 1;
        if (c == 15) { CP_WAIT0(); } else { CP_WAIT1(); }
        __syncthreads();

        const uint32_t bA = sb + s * K2_STAGE;
        const uint32_t bB = bA + 16384;

        #pragma unroll
        for (int ks = 0; ks < 4; ks++) {
            uint32_t a_h[2][4];
            {
                int arow  = wm + (lane & 15);
                int acolb = ks * 32 + ((lane >> 4) << 4);
                #pragma unroll
                for (int mi = 0; mi < 2; mi++) {
                    uint32_t off = SWA((arow + mi * 16) * 128 + acolb);
                    ldsm4(a_h[mi], bA + off);
                }
            }
            int browb = (ks * 16 + (lane & 15)) * 512;
            #pragma unroll
            for (int g = 0; g < 4; g++) {
                uint32_t off = SWC(browb + (wn + g * 16 + ((lane >> 4) << 3)) * 2);
                uint32_t bh[4];
                ldsm4t(bh, bB + off);
                #pragma unroll
                for (int mi = 0; mi < 2; mi++) {
                    mma16816(acc[mi][2*g],   a_h[mi], bh);
                    mma16816(acc[mi][2*g+1], a_h[mi], bh + 2);
                }
            }
        }
        __syncthreads();
        if (c + 2 < 16) load_chunk(c + 2, s);
    }

    const int bz = n0 >> 14;
    const int ncb = n0 & 16383;
    #pragma unroll
    for (int mi = 0; mi < 2; mi++) {
        int r0 = wm + mi * 16 + (lane >> 2);
        float bv0 = bc[r0], bv1 = bc[r0 + 8];
        float* row0 = out + ((size_t)(bz * COUT + r0))     * 16384 + ncb;
        float* row1 = out + ((size_t)(bz * COUT + r0 + 8)) * 16384 + ncb;
        #pragma unroll
        for (int nt = 0; nt < 8; nt++) {
            int col = wn + nt * 8 + (lane & 3) * 2;
            float2 v0, v1;
            v0.x = acc[mi][nt][0] + bv0; v0.y = acc[mi][nt][1] + bv0;
            v1.x = acc[mi][nt][2] + bv1; v1.y = acc[mi][nt][3] + bv1;
            *(float2*)(row0 + col) = v0;
            *(float2*)(row1 + col) = v1;
        }
    }
}

extern "C" void kernel_launch(void* const* d_in, const int* in_sizes, int n_in,
                              void* d_out, int out_size) {
    const float* x  = (const float*)d_in[0];
    const float* r  = (const float*)d_in[1];
    const float* W1 = (const float*)d_in[2];
    const float* b1 = (const float*)d_in[3];
    const float* W2 = (const float*)d_in[4];
    const float* b2 = (const float*)d_in[5];
    const float* Wc = (const float*)d_in[6];
    const float* bc = (const float*)d_in[7];
    float* out = (float*)d_out;

    cudaFuncSetAttribute(k1_weights, cudaFuncAttributeMaxDynamicSharedMemorySize, SM1_BYTES);
    cudaFuncSetAttribute(k2_hmma, cudaFuncAttributeMaxDynamicSharedMemorySize, K2_SMEM);

    float* rcout = (out_size > OUT0) ? (out + OUT0) : nullptr;

    k0_prep<<<(COUT * KTOT + 255) / 256, 256>>>(Wc, W2, W1);
    dim3 g1(32, 32, 4);
    k1_weights<<<g1, 256, SM1_BYTES>>>(x, r, W1, b1, b2, rcout);
    k2_hmma<<<256, 512, K2_SMEM>>>(bc, out);
}

// round 15
// speedup vs baseline: 2.7280x; 1.2066x over previous
#include <cuda_runtime.h>
#include <cuda_fp16.h>
#include <cstdint>
#include <cstddef>

#define BATCH   4
#define CIN     64
#define COUT    128
#define HH      64
#define WW      1024
#define HO      32
#define WO      512
#define NPIX    65536
#define KTOT    1024
#define OUT0    8388608
#define AZI_C   0.006135923151542565f
#define INC_C   0.0073f

__device__ __half g_m[(size_t)KTOT * NPIX];     // single fp16 plane
__device__ __half g_WcH[COUT * KTOT];           // fp16(Wc)
__device__ __half g_W2TH[CIN * CIN];            // fp16(W2^T) [c][j]
__device__ float  g_Ast[CIN * 16];              // [j][pos]

__device__ __forceinline__ uint32_t smem_u32(const void* p) {
    uint32_t a;
    asm("{ .reg .u64 t; cvta.to.shared.u64 t, %1; cvt.u32.u64 %0, t; }" : "=r"(a) : "l"(p));
    return a;
}
#define SWA(o) ((o) ^ (((o) >> 3) & 0x70))
#define SWC(o) ((o) ^ (((o) >> 5) & 0x70))

__device__ __forceinline__ void sts32(uint32_t saddr, uint32_t v) {
    asm volatile("st.shared.u32 [%0], %1;" :: "r"(saddr), "r"(v) : "memory");
}
__device__ __forceinline__ float lds_h16(uint32_t saddr) {
    float v;
    asm volatile("{ .reg .b16 h; ld.shared.b16 h, [%1]; cvt.f32.f16 %0, h; }"
        : "=f"(v) : "r"(saddr));
    return v;
}
__device__ __forceinline__ void cp16(uint32_t saddr, const void* gaddr) {
    asm volatile("cp.async.cg.shared.global [%0], [%1], 16;" :: "r"(saddr), "l"(gaddr));
}
#define CP_COMMIT() asm volatile("cp.async.commit_group;" ::: "memory")
#define CP_WAIT1()  asm volatile("cp.async.wait_group 1;" ::: "memory")
#define CP_WAIT0()  asm volatile("cp.async.wait_group 0;" ::: "memory")

__device__ __forceinline__ void ldsm4(uint32_t* r, uint32_t a) {
    asm volatile("ldmatrix.sync.aligned.m8n8.x4.shared.b16 {%0,%1,%2,%3}, [%4];"
        : "=r"(r[0]), "=r"(r[1]), "=r"(r[2]), "=r"(r[3]) : "r"(a));
}
__device__ __forceinline__ void ldsm4t(uint32_t* r, uint32_t a) {
    asm volatile("ldmatrix.sync.aligned.m8n8.x4.trans.shared.b16 {%0,%1,%2,%3}, [%4];"
        : "=r"(r[0]), "=r"(r[1]), "=r"(r[2]), "=r"(r[3]) : "r"(a));
}
__device__ __forceinline__ void mma16816(float* d, const uint32_t* a, const uint32_t* b) {
    asm volatile(
        "mma.sync.aligned.m16n8k16.row.col.f32.f16.f16.f32 "
        "{%0,%1,%2,%3}, {%4,%5,%6,%7}, {%8,%9}, {%0,%1,%2,%3};"
        : "+f"(d[0]), "+f"(d[1]), "+f"(d[2]), "+f"(d[3])
        : "r"(a[0]), "r"(a[1]), "r"(a[2]), "r"(a[3]), "r"(b[0]), "r"(b[1]));
}
__device__ __forceinline__ uint32_t pk_h2(float lo, float hi) {
    uint32_t r;
    asm("cvt.rn.f16x2.f32 %0, %1, %2;" : "=r"(r) : "f"(hi), "f"(lo));
    return r;
}

// =====================================================================
// Kernel 0: fp16(Wc), fp16(W2^T), Ast
// =====================================================================
__global__ void k0_prep(const float* __restrict__ Wc, const float* __restrict__ W2,
                        const float* __restrict__ W1) {
    int i = blockIdx.x * 256 + threadIdx.x;
    if (i < COUT * KTOT) {
        g_WcH[i] = __float2half_rn(Wc[i]);
    }
    if (i < CIN * CIN) {
        int j = i >> 6, c = i & 63;
        g_W2TH[c * 64 + j] = __float2half_rn(W2[i]);
    }
    if (i < CIN * 16) {
        int j = i >> 4, pos = i & 15;
        int u = pos >> 2, v = pos & 3;
        float du = (float)(u - 2), dv = (float)(v - 2);
        float ca = cosf(AZI_C * dv), sa = sinf(AZI_C * dv);
        float ci = cosf(INC_C * du), si = sinf(INC_C * du);
        g_Ast[i] = ca * ci * W1[j] + ca * si * W1[64 + j] + sa * W1[128 + j];
    }
}

// =====================================================================
// Kernel 1 v6: fp16 path, 1-combo w-GEMM, w stored fp16, 3 CTAs/SM.
// 16-px tile, 256 threads, grid (32, 32, 4).
// smem map (46368 B):
//   0     HS/WS fp16 [64][512B SWC rows] (32768, time-shared h -> w)
//   32768 W2TH (8192)
//   40960 Ast (4096)
//   45056 W10 (256) | 45312 b1 (256) | 45568 b2 (256)
//   45824 rs [4][34] (544)
// =====================================================================
#define V6_HS    0
#define V6_W2TH  32768
#define V6_AST   40960
#define V6_W10   45056
#define V6_B1    45312
#define V6_B2    45568
#define V6_RS    45824
#define SM1_BYTES 46368

__global__ void __launch_bounds__(256, 3)
k1_weights(const float* __restrict__ x, const float* __restrict__ r,
           const float* __restrict__ W1, const float* __restrict__ b1,
           const float* __restrict__ b2, float* __restrict__ rcout)
{
    extern __shared__ float sm[];
    float* Ast  = sm + V6_AST / 4;
    float* W10s = sm + V6_W10 / 4;
    float* b1s  = sm + V6_B1 / 4;
    float* b2s  = sm + V6_B2 / 4;
    float* rs   = sm + V6_RS / 4;
    char*  smc  = (char*)sm;
    const uint32_t sb = smem_u32(sm);

    const int tid  = threadIdx.x;
    const int lane = tid & 31;
    const int wid  = tid >> 5;
    const int ho   = blockIdx.y;
    const int bz   = blockIdx.z;
    const int wo0  = blockIdx.x * 16;

    if (tid < 64) { W10s[tid] = W1[tid]; b1s[tid] = b1[tid]; b2s[tid] = b2[tid]; }
    for (int i = tid; i < 1024; i += 256) Ast[i] = g_Ast[i];
    if (tid < 4 * 34) {
        int v = tid / 34, cc = tid % 34;
        int rowp = 2 * ho + v;
        int row  = (rowp == 0) ? (HH - 1) : ((rowp == HH + 1) ? 0 : rowp - 1);
        int colp = 2 * wo0 + cc;
        float val;
        if (colp == 0 || colp == WW + 1) val = 100.0f;
        else val = r[((size_t)bz * HH + row) * WW + (colp - 1)];
        rs[tid] = val;
    }
    for (int i = tid; i < 4096; i += 256) {
        int row = i >> 6, col = i & 63;
        uint32_t off = SWA(row * 128 + col * 2);
        *(__half*)(smc + V6_W2TH + off) = g_W2TH[i];
    }
    __syncthreads();

    const size_t nbase = (size_t)bz * 16384 + (size_t)ho * 512 + wo0;

    // ---- h compute -> fp16 plane in HS ----
    {
        int pos = tid >> 4;
        int u = pos >> 2, v = pos & 3;
        int px = tid & 15;
        float R   = rs[v * 34 + 2 * px + u];
        float nrc = -rs[2 * 34 + 2 * px + 2];
        const int wordb = (tid & ~1) * 2;
        const bool evenl = ((lane & 1) == 0);
        #pragma unroll 8
        for (int j = 0; j < 64; j++) {
            float t = fmaf(R, Ast[j * 16 + pos], fmaf(nrc, W10s[j], b1s[j]));
            t = (t > 0.0f) ? t : 0.2f * t;
            float t_o = __shfl_xor_sync(0xffffffffu, t, 1);
            if (evenl) {
                uint32_t word = pk_h2(t, t_o);
                sts32(sb + V6_HS + SWC(j * 512 + wordb), word);
            }
        }
    }
    __syncthreads();

    // ---- w-GEMM: 8 warps, M16(c) x N128(combo), K=64, 1 combo ----
    {
        const int wm = (wid & 3) * 16;
        const int wn = (wid >> 2) * 128;

        float acc[16][4];
        #pragma unroll
        for (int nt = 0; nt < 16; nt++)
            #pragma unroll
            for (int q = 0; q < 4; q++) acc[nt][q] = 0.0f;

        #pragma unroll
        for (int ks = 0; ks < 4; ks++) {
            uint32_t aH[4];
            int arow  = wm + (lane & 15);
            int acolb = ks * 32 + ((lane >> 4) << 4);
            ldsm4(aH, sb + V6_W2TH + SWA(arow * 128 + acolb));
            int browb = (ks * 16 + (lane & 15)) * 512;
            #pragma unroll
            for (int g = 0; g < 8; g++) {
                uint32_t off = SWC(browb + wn * 2 + g * 32 + ((lane >> 4) << 4));
                uint32_t bh[4];
                ldsm4t(bh, sb + V6_HS + off);
                mma16816(acc[2*g],   aH, bh);
                mma16816(acc[2*g+1], aH, bh + 2);
            }
        }
        __syncthreads();   // h fully consumed; region becomes w

        // w = acc + b2 -> fp16 plane (same region)
        int r0 = wm + (lane >> 2);
        int r2 = r0 + 8;
        float b2a = b2s[r0], b2b = b2s[r2];
        #pragma unroll
        for (int nt = 0; nt < 16; nt++) {
            int col = wn + nt * 8 + (lane & 3) * 2;     // even col
            uint32_t w01 = pk_h2(acc[nt][0] + b2a, acc[nt][1] + b2a);
            uint32_t w23 = pk_h2(acc[nt][2] + b2b, acc[nt][3] + b2b);
            sts32(sb + V6_HS + SWC(r0 * 512 + col * 2), w01);
            sts32(sb + V6_HS + SWC(r2 * 512 + col * 2), w23);
        }
    }
    __syncthreads();

    // ---- phase B: m = w * x -> g_m (fp16) ----
    {
        int pos = 2 * wid + (lane >> 4);
        int u = pos >> 2, v = pos & 3;
        int px = lane & 15;
        int comb = pos * 16 + px;

        int rowp = 2 * ho + v;
        int xrow = (rowp == 0) ? (HH - 1) : ((rowp == HH + 1) ? 0 : rowp - 1);
        int xcol = 2 * (wo0 + px) + u - 1;
        bool valid = (xcol >= 0) && (xcol < WW);
        const float* xbase = x + ((size_t)(bz * CIN) * HH + xrow) * WW + (valid ? xcol : 0);

        __half* gm = g_m + (size_t)pos * NPIX + nbase + px;
        #pragma unroll 8
        for (int c = 0; c < 64; c++) {
            float wv = lds_h16(sb + V6_HS + SWC(c * 512 + comb * 2));
            float xv = valid ? xbase[(size_t)c * (HH * WW)] : 0.0f;
            gm[(size_t)c * 16 * NPIX] = __float2half_rn(wv * xv);
        }
    }

    if (rcout != nullptr && tid < 16) {
        rcout[nbase + tid] = rs[2 * 34 + 2 * tid + 2];
    }
}

// =====================================================================
// Kernel 2 (unchanged from R14): fp16 1-combo GEMM.
// =====================================================================
#define K2_STAGE 49152
#define K2_SMEM  (2 * K2_STAGE)

__global__ void __launch_bounds__(512, 1)
k2_hmma(const float* __restrict__ bc, float* __restrict__ out)
{
    extern __shared__ char sm2[];
    const uint32_t sb = smem_u32(sm2);
    const int tid  = threadIdx.x;
    const int wid  = tid >> 5;
    const int lane = tid & 31;
    const int n0 = blockIdx.x * 256;
    const int wm = (wid & 3) * 32;
    const int wn = (wid >> 2) * 64;

    float acc[2][8][4];
    #pragma unroll
    for (int mi = 0; mi < 2; mi++)
        #pragma unroll
        for (int nt = 0; nt < 8; nt++)
            #pragma unroll
            for (int q = 0; q < 4; q++) acc[mi][nt][q] = 0.0f;

    auto load_chunk = [&](int c, int s) {
        const uint32_t base = sb + s * K2_STAGE;
        const int k0 = c * 64;
        #pragma unroll
        for (int t = 0; t < 2; t++) {
            int ci = tid + t * 512;
            int row = ci >> 3, un = ci & 7;
            uint32_t sa = base + SWA(row * 128 + un * 16);
            cp16(sa, g_WcH + (size_t)row * KTOT + k0 + un * 8);
        }
        #pragma unroll
        for (int t = 0; t < 4; t++) {
            int ci = tid + t * 512;
            int row = ci >> 5, un = ci & 31;
            uint32_t sa = base + 16384 + SWC(row * 512 + un * 16);
            cp16(sa, g_m + (size_t)(k0 + row) * NPIX + n0 + un * 8);
        }
        CP_COMMIT();
    };

    load_chunk(0, 0);
    load_chunk(1, 1);

    for (int c = 0; c < 16; c++) {
        const int s = c & 1;
        if (c == 15) { CP_WAIT0(); } else { CP_WAIT1(); }
        __syncthreads();

        const uint32_t bA = sb + s * K2_STAGE;
        const uint32_t bB = bA + 16384;

        #pragma unroll
        for (int ks = 0; ks < 4; ks++) {
            uint32_t a_h[2][4];
            {
                int arow  = wm + (lane & 15);
                int acolb = ks * 32 + ((lane >> 4) << 4);
                #pragma unroll
                for (int mi = 0; mi < 2; mi++) {
                    uint32_t off = SWA((arow + mi * 16) * 128 + acolb);
                    ldsm4(a_h[mi], bA + off);
                }
            }
            int browb = (ks * 16 + (lane & 15)) * 512;
            #pragma unroll
            for (int g = 0; g < 4; g++) {
                uint32_t off = SWC(browb + (wn + g * 16 + ((lane >> 4) << 3)) * 2);
                uint32_t bh[4];
                ldsm4t(bh, bB + off);
                #pragma unroll
                for (int mi = 0; mi < 2; mi++) {
                    mma16816(acc[mi][2*g],   a_h[mi], bh);
                    mma16816(acc[mi][2*g+1], a_h[mi], bh + 2);
                }
            }
        }
        __syncthreads();
        if (c + 2 < 16) load_chunk(c + 2, s);
    }

    const int bz = n0 >> 14;
    const int ncb = n0 & 16383;
    #pragma unroll
    for (int mi = 0; mi < 2; mi++) {
        int r0 = wm + mi * 16 + (lane >> 2);
        float bv0 = bc[r0], bv1 = bc[r0 + 8];
        float* row0 = out + ((size_t)(bz * COUT + r0))     * 16384 + ncb;
        float* row1 = out + ((size_t)(bz * COUT + r0 + 8)) * 16384 + ncb;
        #pragma unroll
        for (int nt = 0; nt < 8; nt++) {
            int col = wn + nt * 8 + (lane & 3) * 2;
            float2 v0, v1;
            v0.x = acc[mi][nt][0] + bv0; v0.y = acc[mi][nt][1] + bv0;
            v1.x = acc[mi][nt][2] + bv1; v1.y = acc[mi][nt][3] + bv1;
            *(float2*)(row0 + col) = v0;
            *(float2*)(row1 + col) = v1;
        }
    }
}

extern "C" void kernel_launch(void* const* d_in, const int* in_sizes, int n_in,
                              void* d_out, int out_size) {
    const float* x  = (const float*)d_in[0];
    const float* r  = (const float*)d_in[1];
    const float* W1 = (const float*)d_in[2];
    const float* b1 = (const float*)d_in[3];
    const float* W2 = (const float*)d_in[4];
    const float* b2 = (const float*)d_in[5];
    const float* Wc = (const float*)d_in[6];
    const float* bc = (const float*)d_in[7];
    float* out = (float*)d_out;

    cudaFuncSetAttribute(k1_weights, cudaFuncAttributeMaxDynamicSharedMemorySize, SM1_BYTES);
    cudaFuncSetAttribute(k2_hmma, cudaFuncAttributeMaxDynamicSharedMemorySize, K2_SMEM);

    float* rcout = (out_size > OUT0) ? (out + OUT0) : nullptr;

    k0_prep<<<(COUT * KTOT + 255) / 256, 256>>>(Wc, W2, W1);
    dim3 g1(32, 32, 4);
    k1_weights<<<g1, 256, SM1_BYTES>>>(x, r, W1, b1, b2, rcout);
    k2_hmma<<<256, 512, K2_SMEM>>>(bc, out);
}